// round 6
// baseline (speedup 1.0000x reference)
#include <cuda_runtime.h>
#include <math.h>

#define NPTS 1024
#define DIM  64
#define HID  256
#define K    16
#define QB   4            // queries per block
#define RB   (QB * K)     // 64 pair rows per block
#define GRID 256
#define NT   256

typedef unsigned long long ull;

__device__ float g_k[NPTS * DIM];
__device__ float g_v[NPTS * DIM];
__device__ unsigned g_bar;   // zero-initialized; advances by GRID per launch

// ---------------- packed fp32x2 helpers ----------------
__device__ __forceinline__ ull fma2(ull a, ull b, ull c) {
    ull d; asm("fma.rn.f32x2 %0, %1, %2, %3;" : "=l"(d) : "l"(a), "l"(b), "l"(c));
    return d;
}
__device__ __forceinline__ ull dup2(float x) {
    ull d; asm("mov.b64 %0, {%1, %1};" : "=l"(d) : "f"(x)); return d;
}
__device__ __forceinline__ ull pack2(float x, float y) {
    ull d; asm("mov.b64 %0, {%1, %2};" : "=l"(d) : "f"(x), "f"(y)); return d;
}
__device__ __forceinline__ float2 up2(ull v) {
    float2 r; asm("mov.b64 {%0, %1}, %2;" : "=f"(r.x), "=f"(r.y) : "l"(v)); return r;
}

// ---------------------------------------------------------------------------
// Fused kernel. grid 256, block 256, 96KB dynamic smem -> 2 blocks/SM.
// Dynamic smem (floats):
//   [0     , 4096 )  T (64x64; later aliased as SIM)
//   [4096  , 8192 )  VG (64x64)
//   [8192  , 16384)  Hh (64x128); E aliases [8192,12288); P2i aliases [12288,16384)
//   [16384 , 24576)  A2s (interleaved half of A2); ps (3072) aliases early
// ---------------------------------------------------------------------------
#define SMEM_FLOATS 24576

__global__ __launch_bounds__(NT, 2)
void fused_kernel(const float* __restrict__ x,
                  const float* __restrict__ pos,
                  const float* __restrict__ Wq,
                  const float* __restrict__ Wk,
                  const float* __restrict__ Wv,
                  const float* __restrict__ P1, const float* __restrict__ pb1,
                  const float* __restrict__ P2, const float* __restrict__ pb2,
                  const float* __restrict__ A1, const float* __restrict__ ab1,
                  const float* __restrict__ A2, const float* __restrict__ ab2,
                  float* __restrict__ out) {
    extern __shared__ float sm[];
    float* T   = sm;                 // 64 x 64
    float* VG  = sm + 4096;          // 64 x 64
    float* Hh  = sm + 8192;          // 64 x 128
    float* E   = Hh;                 // 64 x 64 (phase 1 only)
    float* P2i = Hh + 4096;          // 4096 (phase 1 only)
    float* A2s = sm + 16384;         // 8192 (per-half interleaved A2)
    float* ps  = sm + 16384;         // aliases A2s during prolog

    __shared__ int   nb[RB];
    __shared__ float rp[RB][3];
    __shared__ float qrow[QB * DIM];
    __shared__ float xs[QB * DIM];
    __shared__ float cval[QB][2][K];
    __shared__ int   cidx[QB][2][K];
    __shared__ unsigned s_ticket;

    int tid = threadIdx.x;
    int ib = blockIdx.x * QB;
    int w = tid >> 5, lane = tid & 31;

    // ---- Step 0: stage pos, x rows, P2 interleaved ----
    for (int t = tid; t < NPTS * 3; t += NT) ps[t] = pos[t];
    xs[tid] = x[ib * DIM + tid];                 // QB*DIM == NT == 256
    for (int t = tid; t < 4096; t += NT) {
        int s = t & 1, d = (t >> 1) & 63, h2 = t >> 7;
        P2i[t] = P2[(2 * h2 + s) * DIM + d];
    }
    __syncthreads();

    // ---- Step 1: qkv for this block's 4 rows ----
    {
        int r = tid >> 6, d = tid & 63;
        float q = 0.f, kk = 0.f, vv = 0.f;
#pragma unroll 4
        for (int c = 0; c < DIM; c++) {
            float xv = xs[r * DIM + c];
            q  += xv * Wq[c * DIM + d];
            kk += xv * Wk[c * DIM + d];
            vv += xv * Wv[c * DIM + d];
        }
        qrow[r * DIM + d] = q;
        g_k[(ib + r) * DIM + d] = kk;
        g_v[(ib + r) * DIM + d] = vv;
    }
    __syncthreads();
    if (tid == 0) {
        __threadfence();
        s_ticket = atomicAdd(&g_bar, 1u);
    }

    // ---- Step 2: kNN for 4 queries (2 warps per query, 512 candidates each) ----
    {
        int qq = w >> 1, hh = w & 1;
        int gi = ib + qq;
        float px = ps[gi * 3 + 0], py = ps[gi * 3 + 1], pz = ps[gi * 3 + 2];
        float v[16]; int id[16];
#pragma unroll
        for (int c = 0; c < 16; c++) {
            int j = hh * 512 + c * 32 + lane;
            float dx = px - ps[j * 3 + 0];
            float dy = py - ps[j * 3 + 1];
            float dz = pz - ps[j * 3 + 2];
            v[c] = dx * dx + dy * dy + dz * dz;
            id[c] = j;
        }
        for (int r = 0; r < K; r++) {
            float bv = v[0]; int bi = id[0];
#pragma unroll
            for (int c = 1; c < 16; c++)
                if (v[c] < bv || (v[c] == bv && id[c] < bi)) { bv = v[c]; bi = id[c]; }
#pragma unroll
            for (int off = 16; off > 0; off >>= 1) {
                float ov = __shfl_down_sync(0xffffffffu, bv, off);
                int   oi = __shfl_down_sync(0xffffffffu, bi, off);
                if (ov < bv || (ov == bv && oi < bi)) { bv = ov; bi = oi; }
            }
            bv = __shfl_sync(0xffffffffu, bv, 0);
            bi = __shfl_sync(0xffffffffu, bi, 0);
            if (lane == 0) { cval[qq][hh][r] = bv; cidx[qq][hh][r] = bi; }
#pragma unroll
            for (int c = 0; c < 16; c++) if (id[c] == bi) v[c] = 3.4e38f;
        }
    }
    __syncthreads();
    // merge the two halves per query: even warps, 32 candidates on 32 lanes
    if ((w & 1) == 0) {
        int qq = w >> 1;
        float mv = cval[qq][lane >> 4][lane & 15];
        int   mi = cidx[qq][lane >> 4][lane & 15];
        for (int r = 0; r < K; r++) {
            float bv = mv; int bi = mi;
#pragma unroll
            for (int off = 16; off > 0; off >>= 1) {
                float ov = __shfl_down_sync(0xffffffffu, bv, off);
                int   oi = __shfl_down_sync(0xffffffffu, bi, off);
                if (ov < bv || (ov == bv && oi < bi)) { bv = ov; bi = oi; }
            }
            bi = __shfl_sync(0xffffffffu, bi, 0);
            if (lane == 0) nb[qq * K + r] = bi;
            if (mi == bi) mv = 3.4e38f;
        }
    }
    __syncthreads();

    // rel_pos from staged ps (before A2s overwrites it)
    if (tid < RB * 3) {
        int r = tid / 3, c = tid - r * 3;
        int gi = ib + (r >> 4);
        rp[r][c] = ps[gi * 3 + c] - ps[nb[r] * 3 + c];
    }
    __syncthreads();

    // ---- Step 3: stage A2s half-0 (overwrites ps); tid0 waits on barrier ----
    for (int t = tid; t < 8192; t += NT) {
        int s = t & 1, d = (t >> 1) & 63, e2l = t >> 7;
        A2s[t] = A2[(2 * e2l + s) * DIM + d];
    }
    if (tid == 0) {
        unsigned target = (s_ticket / GRID + 1u) * GRID;
        while ((int)(*(volatile unsigned*)&g_bar - target) < 0) { }
        __threadfence();
    }
    __syncthreads();

    // ---- Phase 1a: E = relu(rp @ P1 + pb1) ----
    for (int t = tid; t < RB * 64; t += NT) {
        int r = t >> 6, h = t & 63;
        float e = rp[r][0] * P1[h] + rp[r][1] * P1[64 + h]
                + rp[r][2] * P1[128 + h] + pb1[h];
        E[t] = fmaxf(e, 0.f);
    }
    __syncthreads();

    int r0 = w * 8;                  // 8 warps x 8 rows = 64 rows
    int d0 = lane, d1 = lane + 32;

    // ---- Phase 1b: rpe = E @ P2 + pb2 ; T = q - k + rpe ; VG = v + rpe ----
    {
        ull aA[8], aB[8];
#pragma unroll
        for (int u = 0; u < 8; u++) { aA[u] = 0ULL; aB[u] = 0ULL; }
#pragma unroll 4
        for (int h2 = 0; h2 < 32; h2 += 2) {
            ull p00 = *(const ull*)(P2i + (((h2 << 6) + d0) << 1));
            ull p01 = *(const ull*)(P2i + (((h2 << 6) + d1) << 1));
            ull p10 = *(const ull*)(P2i + ((((h2 + 1) << 6) + d0) << 1));
            ull p11 = *(const ull*)(P2i + ((((h2 + 1) << 6) + d1) << 1));
#pragma unroll
            for (int u = 0; u < 8; u++) {
                ulonglong2 ev = *(const ulonglong2*)(E + ((r0 + u) << 6) + (h2 << 1));
                aA[u] = fma2(ev.x, p00, aA[u]);
                aB[u] = fma2(ev.x, p01, aB[u]);
                aA[u] = fma2(ev.y, p10, aA[u]);
                aB[u] = fma2(ev.y, p11, aB[u]);
            }
        }
        float b0 = pb2[d0], b1 = pb2[d1];
#pragma unroll
        for (int u = 0; u < 8; u++) {
            int r = r0 + u;
            int j = nb[r];
            int qq = r >> 4;
            float2 fa = up2(aA[u]); float rpe0 = fa.x + fa.y + b0;
            float2 fb = up2(aB[u]); float rpe1 = fb.x + fb.y + b1;
            T[r * 64 + d0]  = qrow[qq * 64 + d0] - g_k[j * 64 + d0] + rpe0;
            VG[r * 64 + d0] = g_v[j * 64 + d0] + rpe0;
            T[r * 64 + d1]  = qrow[qq * 64 + d1] - g_k[j * 64 + d1] + rpe1;
            VG[r * 64 + d1] = g_v[j * 64 + d1] + rpe1;
        }
    }
    __syncthreads();

    // ---- Phases 2+3 over two e-halves; phase-3 accumulators persist ----
    ull sA[8], sB[8];
#pragma unroll
    for (int u = 0; u < 8; u++) { sA[u] = 0ULL; sB[u] = 0ULL; }
    int e0 = lane << 2;

    for (int half = 0; half < 2; half++) {
        if (half == 1) {
            // restage A2s for half 1 (phase 3 of half 0 is done; sync above)
            for (int t = tid; t < 8192; t += NT) {
                int s = t & 1, d = (t >> 1) & 63, e2l = t >> 7;
                A2s[t] = A2[(128 + 2 * e2l + s) * DIM + d];
            }
            __syncthreads();
        }
        // Phase 2: Hh = relu(T @ A1[:, half*128 +128) + ab1)
        {
            const float* A1h = A1 + half * 128 + e0;
            float4 b = *(const float4*)(ab1 + half * 128 + e0);
            ull acc0[8], acc1[8];
#pragma unroll
            for (int u = 0; u < 8; u++) {
                acc0[u] = pack2(b.x, b.y);
                acc1[u] = pack2(b.z, b.w);
            }
#pragma unroll 4
            for (int d2 = 0; d2 < 32; d2++) {
                ulonglong2 av0 = *(const ulonglong2*)(A1h + (2 * d2) * HID);
                ulonglong2 av1 = *(const ulonglong2*)(A1h + (2 * d2 + 1) * HID);
#pragma unroll
                for (int u = 0; u < 8; u++) {
                    float2 tp = *(const float2*)(T + ((r0 + u) << 6) + 2 * d2);
                    ull t0 = dup2(tp.x);
                    ull t1 = dup2(tp.y);
                    acc0[u] = fma2(t0, av0.x, acc0[u]);
                    acc1[u] = fma2(t0, av0.y, acc1[u]);
                    acc0[u] = fma2(t1, av1.x, acc0[u]);
                    acc1[u] = fma2(t1, av1.y, acc1[u]);
                }
            }
#pragma unroll
            for (int u = 0; u < 8; u++) {
                float2 h0 = up2(acc0[u]);
                float2 h1 = up2(acc1[u]);
                float4 hv = make_float4(fmaxf(h0.x, 0.f), fmaxf(h0.y, 0.f),
                                        fmaxf(h1.x, 0.f), fmaxf(h1.y, 0.f));
                *(float4*)(Hh + ((r0 + u) << 7) + e0) = hv;
            }
        }
        __syncthreads();

        // Phase 3 accumulate: SIM += Hh @ A2s (this half)
#pragma unroll 2
        for (int e2l = 0; e2l < 64; e2l += 2) {
            ull a00 = *(const ull*)(A2s + (((e2l << 6) + d0) << 1));
            ull a01 = *(const ull*)(A2s + (((e2l << 6) + d1) << 1));
            ull a10 = *(const ull*)(A2s + ((((e2l + 1) << 6) + d0) << 1));
            ull a11 = *(const ull*)(A2s + ((((e2l + 1) << 6) + d1) << 1));
#pragma unroll
            for (int u = 0; u < 8; u++) {
                ulonglong2 hv = *(const ulonglong2*)(Hh + ((r0 + u) << 7) + (e2l << 1));
                sA[u] = fma2(hv.x, a00, sA[u]);
                sB[u] = fma2(hv.x, a01, sB[u]);
                sA[u] = fma2(hv.y, a10, sA[u]);
                sB[u] = fma2(hv.y, a11, sB[u]);
            }
        }
        __syncthreads();
    }

    // ---- Phase 3 epilogue: SIM (aliases T) ----
    {
        float b0 = ab2[d0], b1 = ab2[d1];
#pragma unroll
        for (int u = 0; u < 8; u++) {
            int r = r0 + u;
            float2 fa = up2(sA[u]);
            float2 fb = up2(sB[u]);
            T[r * 64 + d0] = fa.x + fa.y + b0;
            T[r * 64 + d1] = fb.x + fb.y + b1;
        }
    }
    __syncthreads();

    // ---- Phase 4: softmax over K neighbors + weighted sum of VG ----
    {
        int qq = tid >> 6, d = tid & 63;
        int base = qq * K;
        float m = -3.4e38f;
#pragma unroll
        for (int kk = 0; kk < K; kk++) m = fmaxf(m, T[(base + kk) * 64 + d]);
        float s = 0.f, agg = 0.f;
#pragma unroll
        for (int kk = 0; kk < K; kk++) {
            float wv = __expf(T[(base + kk) * 64 + d] - m);
            s += wv;
            agg += wv * VG[(base + kk) * 64 + d];
        }
        out[(ib + qq) * 64 + d] = agg / s;
    }
}

// ---------------------------------------------------------------------------
extern "C" void kernel_launch(void* const* d_in, const int* in_sizes, int n_in,
                              void* d_out, int out_size) {
    const float* x   = (const float*)d_in[0];
    const float* pos = (const float*)d_in[1];
    const float* Wq  = (const float*)d_in[2];
    const float* Wk  = (const float*)d_in[3];
    const float* Wv  = (const float*)d_in[4];
    const float* P1  = (const float*)d_in[5];
    const float* pb1 = (const float*)d_in[6];
    const float* P2  = (const float*)d_in[7];
    const float* pb2 = (const float*)d_in[8];
    const float* A1  = (const float*)d_in[9];
    const float* ab1 = (const float*)d_in[10];
    const float* A2  = (const float*)d_in[11];
    const float* ab2 = (const float*)d_in[12];
    float* out = (float*)d_out;

    cudaFuncSetAttribute(fused_kernel, cudaFuncAttributeMaxDynamicSharedMemorySize,
                         SMEM_FLOATS * sizeof(float));
    fused_kernel<<<GRID, NT, SMEM_FLOATS * sizeof(float)>>>(
        x, pos, Wq, Wk, Wv, P1, pb1, P2, pb2, A1, ab1, A2, ab2, out);
}

// round 8
// speedup vs baseline: 1.0344x; 1.0344x over previous
#include <cuda_runtime.h>
#include <math.h>

#define NPTS 1024
#define DIM  64
#define HID  256
#define K    16
#define QB   8            // queries per block
#define RB   (QB * K)     // 128 pair rows per block
#define GRID 128
#define NT   512

typedef unsigned long long ull;

__device__ float g_k[NPTS * DIM];
__device__ float g_v[NPTS * DIM];
__device__ unsigned g_bar;   // zero-initialized; advances by GRID per launch

// ---------------- packed fp32x2 helpers ----------------
__device__ __forceinline__ ull fma2(ull a, ull b, ull c) {
    ull d; asm("fma.rn.f32x2 %0, %1, %2, %3;" : "=l"(d) : "l"(a), "l"(b), "l"(c));
    return d;
}
__device__ __forceinline__ ull dup2(float x) {
    ull d; asm("mov.b64 %0, {%1, %1};" : "=l"(d) : "f"(x)); return d;
}
__device__ __forceinline__ ull pack2(float x, float y) {
    ull d; asm("mov.b64 %0, {%1, %2};" : "=l"(d) : "f"(x), "f"(y)); return d;
}
__device__ __forceinline__ float2 up2(ull v) {
    float2 r; asm("mov.b64 {%0, %1}, %2;" : "=f"(r.x), "=f"(r.y) : "l"(v)); return r;
}

// ---------------------------------------------------------------------------
// Fused kernel. grid 128, block 512, 192KB dynamic smem.
// Dynamic smem (floats):
//   [0     , 8192 )  T (128x64; later aliased as SIM)
//   [8192  , 16384)  VG (128x64)
//   [16384 , 32768)  Hh (128x128); E aliases [16384,24576); P2i aliases [24576,28672)
//   [32768 , 40960)  A1s (half of A1: 64 x 128)
//   [40960 , 49152)  A2s (interleaved half of A2: 64 e2 x 64 d x 2)
//   ps (3072 floats) aliases [32768, 35840) during prolog
// ---------------------------------------------------------------------------
#define SMEM_FLOATS 49152

__global__ __launch_bounds__(NT)
void fused_kernel(const float* __restrict__ x,
                  const float* __restrict__ pos,
                  const float* __restrict__ Wq,
                  const float* __restrict__ Wk,
                  const float* __restrict__ Wv,
                  const float* __restrict__ P1, const float* __restrict__ pb1,
                  const float* __restrict__ P2, const float* __restrict__ pb2,
                  const float* __restrict__ A1, const float* __restrict__ ab1,
                  const float* __restrict__ A2, const float* __restrict__ ab2,
                  float* __restrict__ out) {
    extern __shared__ float sm[];
    float* T   = sm;                 // 128 x 64
    float* VG  = sm + 8192;          // 128 x 64
    float* Hh  = sm + 16384;         // 128 x 128
    float* E   = Hh;                 // 128 x 64 (phase 1 only)
    float* P2i = Hh + 8192;          // 4096 (phase 1 only)
    float* A1s = sm + 32768;         // 8192: A1 half, [d][e] rows of 128
    float* A2s = sm + 40960;         // 8192: A2 half, interleaved pairs
    float* ps  = sm + 32768;         // aliases A1s region during prolog

    __shared__ int   nb[RB];
    __shared__ float rp[RB][3];
    __shared__ float qrow[QB * DIM];
    __shared__ float xs[QB * DIM];
    __shared__ float cval[QB][2][K];
    __shared__ int   cidx[QB][2][K];
    __shared__ unsigned s_ticket;

    int tid = threadIdx.x;
    int ib = blockIdx.x * QB;
    int w = tid >> 5, lane = tid & 31;

    // ---- Step 0: stage pos, x rows, P2 interleaved ----
    for (int t = tid; t < NPTS * 3; t += NT) ps[t] = pos[t];
    for (int t = tid; t < QB * DIM; t += NT) xs[t] = x[ib * DIM + t];
    for (int t = tid; t < 4096; t += NT) {
        int s = t & 1, d = (t >> 1) & 63, h2 = t >> 7;
        P2i[t] = P2[(2 * h2 + s) * DIM + d];
    }
    __syncthreads();

    // ---- Step 1: qkv for this block's 8 rows ----
    {
        int r = tid >> 6, d = tid & 63;
        float q = 0.f, kk = 0.f, vv = 0.f;
#pragma unroll 4
        for (int c = 0; c < DIM; c++) {
            float xv = xs[r * DIM + c];
            q  += xv * Wq[c * DIM + d];
            kk += xv * Wk[c * DIM + d];
            vv += xv * Wv[c * DIM + d];
        }
        qrow[r * DIM + d] = q;
        g_k[(ib + r) * DIM + d] = kk;
        g_v[(ib + r) * DIM + d] = vv;
    }
    __syncthreads();
    if (tid == 0) {
        __threadfence();
        s_ticket = atomicAdd(&g_bar, 1u);
    }

    // ---- Step 2: kNN for 8 queries (2 warps per query, 512 candidates each) ----
    {
        int qq = w >> 1, hh = w & 1;
        int gi = ib + qq;
        float px = ps[gi * 3 + 0], py = ps[gi * 3 + 1], pz = ps[gi * 3 + 2];
        float v[16]; int id[16];
#pragma unroll
        for (int c = 0; c < 16; c++) {
            int j = hh * 512 + c * 32 + lane;
            float dx = px - ps[j * 3 + 0];
            float dy = py - ps[j * 3 + 1];
            float dz = pz - ps[j * 3 + 2];
            v[c] = dx * dx + dy * dy + dz * dz;
            id[c] = j;
        }
        for (int r = 0; r < K; r++) {
            float bv = v[0]; int bi = id[0];
#pragma unroll
            for (int c = 1; c < 16; c++)
                if (v[c] < bv || (v[c] == bv && id[c] < bi)) { bv = v[c]; bi = id[c]; }
#pragma unroll
            for (int off = 16; off > 0; off >>= 1) {
                float ov = __shfl_down_sync(0xffffffffu, bv, off);
                int   oi = __shfl_down_sync(0xffffffffu, bi, off);
                if (ov < bv || (ov == bv && oi < bi)) { bv = ov; bi = oi; }
            }
            bv = __shfl_sync(0xffffffffu, bv, 0);
            bi = __shfl_sync(0xffffffffu, bi, 0);
            if (lane == 0) { cval[qq][hh][r] = bv; cidx[qq][hh][r] = bi; }
#pragma unroll
            for (int c = 0; c < 16; c++) if (id[c] == bi) v[c] = 3.4e38f;
        }
    }
    __syncthreads();
    // merge the two halves per query: even warps, 32 candidates on 32 lanes
    if ((w & 1) == 0) {
        int qq = w >> 1;
        float mv = cval[qq][lane >> 4][lane & 15];
        int   mi = cidx[qq][lane >> 4][lane & 15];
        for (int r = 0; r < K; r++) {
            float bv = mv; int bi = mi;
#pragma unroll
            for (int off = 16; off > 0; off >>= 1) {
                float ov = __shfl_down_sync(0xffffffffu, bv, off);
                int   oi = __shfl_down_sync(0xffffffffu, bi, off);
                if (ov < bv || (ov == bv && oi < bi)) { bv = ov; bi = oi; }
            }
            bi = __shfl_sync(0xffffffffu, bi, 0);
            if (lane == 0) nb[qq * K + r] = bi;
            if (mi == bi) mv = 3.4e38f;
        }
    }
    __syncthreads();

    // rel_pos from staged ps (before A1s overwrites it)
    for (int t = tid; t < RB * 3; t += NT) {
        int r = t / 3, c = t - r * 3;
        int gi = ib + (r >> 4);
        rp[r][c] = ps[gi * 3 + c] - ps[nb[r] * 3 + c];
    }
    __syncthreads();

    // ---- Step 3: stage A1s/A2s half-0 (overwrites ps); tid0 waits on barrier ----
    for (int t = tid; t < 8192; t += NT) {
        int e = t & 127, d = t >> 7;
        A1s[t] = A1[d * HID + e];
    }
    for (int t = tid; t < 8192; t += NT) {
        int s = t & 1, d = (t >> 1) & 63, e2l = t >> 7;
        A2s[t] = A2[(2 * e2l + s) * DIM + d];
    }
    if (tid == 0) {
        unsigned target = (s_ticket / GRID + 1u) * GRID;
        while ((int)(*(volatile unsigned*)&g_bar - target) < 0) { }
        __threadfence();
    }
    __syncthreads();

    // ---- Phase 1a: E = relu(rp @ P1 + pb1) ----
    for (int t = tid; t < RB * 64; t += NT) {
        int r = t >> 6, h = t & 63;
        float e = rp[r][0] * P1[h] + rp[r][1] * P1[64 + h]
                + rp[r][2] * P1[128 + h] + pb1[h];
        E[t] = fmaxf(e, 0.f);
    }
    __syncthreads();

    int r0 = w * 8;
    int d0 = lane, d1 = lane + 32;

    // ---- Phase 1b: rpe = E @ P2 + pb2 ; T = q - k + rpe ; VG = v + rpe ----
    {
        ull aA[8], aB[8];
#pragma unroll
        for (int u = 0; u < 8; u++) { aA[u] = 0ULL; aB[u] = 0ULL; }
#pragma unroll 4
        for (int h2 = 0; h2 < 32; h2 += 2) {
            ull p00 = *(const ull*)(P2i + (((h2 << 6) + d0) << 1));
            ull p01 = *(const ull*)(P2i + (((h2 << 6) + d1) << 1));
            ull p10 = *(const ull*)(P2i + ((((h2 + 1) << 6) + d0) << 1));
            ull p11 = *(const ull*)(P2i + ((((h2 + 1) << 6) + d1) << 1));
#pragma unroll
            for (int u = 0; u < 8; u++) {
                ulonglong2 ev = *(const ulonglong2*)(E + ((r0 + u) << 6) + (h2 << 1));
                aA[u] = fma2(ev.x, p00, aA[u]);
                aB[u] = fma2(ev.x, p01, aB[u]);
                aA[u] = fma2(ev.y, p10, aA[u]);
                aB[u] = fma2(ev.y, p11, aB[u]);
            }
        }
        float b0 = pb2[d0], b1 = pb2[d1];
#pragma unroll
        for (int u = 0; u < 8; u++) {
            int r = r0 + u;
            int j = nb[r];
            int qq = r >> 4;
            float2 fa = up2(aA[u]); float rpe0 = fa.x + fa.y + b0;
            float2 fb = up2(aB[u]); float rpe1 = fb.x + fb.y + b1;
            T[r * 64 + d0]  = qrow[qq * 64 + d0] - g_k[j * 64 + d0] + rpe0;
            VG[r * 64 + d0] = g_v[j * 64 + d0] + rpe0;
            T[r * 64 + d1]  = qrow[qq * 64 + d1] - g_k[j * 64 + d1] + rpe1;
            VG[r * 64 + d1] = g_v[j * 64 + d1] + rpe1;
        }
    }
    __syncthreads();

    // ---- Phases 2+3 over two e-halves; phase-3 accumulators persist ----
    ull sA[8], sB[8];
#pragma unroll
    for (int u = 0; u < 8; u++) { sA[u] = 0ULL; sB[u] = 0ULL; }
    int e0 = lane << 2;

    for (int half = 0; half < 2; half++) {
        if (half == 1) {
            // restage A1s/A2s for half 1
            for (int t = tid; t < 8192; t += NT) {
                int e = t & 127, d = t >> 7;
                A1s[t] = A1[d * HID + 128 + e];
            }
            for (int t = tid; t < 8192; t += NT) {
                int s = t & 1, d = (t >> 1) & 63, e2l = t >> 7;
                A2s[t] = A2[(128 + 2 * e2l + s) * DIM + d];
            }
            __syncthreads();
        }
        // Phase 2: Hh = relu(T @ A1s + ab1_half), A1 half from smem
        {
            const float* A1p = A1s + e0;
            float4 b = *(const float4*)(ab1 + half * 128 + e0);
            ull acc0[8], acc1[8];
#pragma unroll
            for (int u = 0; u < 8; u++) {
                acc0[u] = pack2(b.x, b.y);
                acc1[u] = pack2(b.z, b.w);
            }
#pragma unroll 2
            for (int d4 = 0; d4 < 16; d4++) {
                ulonglong2 av0 = *(const ulonglong2*)(A1p + (d4 * 4 + 0) * 128);
                ulonglong2 av1 = *(const ulonglong2*)(A1p + (d4 * 4 + 1) * 128);
                ulonglong2 av2 = *(const ulonglong2*)(A1p + (d4 * 4 + 2) * 128);
                ulonglong2 av3 = *(const ulonglong2*)(A1p + (d4 * 4 + 3) * 128);
#pragma unroll
                for (int u = 0; u < 8; u++) {
                    float4 tv = *(const float4*)(T + ((r0 + u) << 6) + (d4 << 2));
                    ull t0 = dup2(tv.x), t1 = dup2(tv.y);
                    ull t2 = dup2(tv.z), t3 = dup2(tv.w);
                    acc0[u] = fma2(t0, av0.x, acc0[u]);
                    acc1[u] = fma2(t0, av0.y, acc1[u]);
                    acc0[u] = fma2(t1, av1.x, acc0[u]);
                    acc1[u] = fma2(t1, av1.y, acc1[u]);
                    acc0[u] = fma2(t2, av2.x, acc0[u]);
                    acc1[u] = fma2(t2, av2.y, acc1[u]);
                    acc0[u] = fma2(t3, av3.x, acc0[u]);
                    acc1[u] = fma2(t3, av3.y, acc1[u]);
                }
            }
#pragma unroll
            for (int u = 0; u < 8; u++) {
                float2 h0 = up2(acc0[u]);
                float2 h1 = up2(acc1[u]);
                float4 hv = make_float4(fmaxf(h0.x, 0.f), fmaxf(h0.y, 0.f),
                                        fmaxf(h1.x, 0.f), fmaxf(h1.y, 0.f));
                *(float4*)(Hh + ((r0 + u) << 7) + e0) = hv;
            }
        }
        __syncthreads();

        // Phase 3 accumulate: SIM += Hh @ A2s (this half)
#pragma unroll 2
        for (int e2l = 0; e2l < 64; e2l += 2) {
            ull a00 = *(const ull*)(A2s + (((e2l << 6) + d0) << 1));
            ull a01 = *(const ull*)(A2s + (((e2l << 6) + d1) << 1));
            ull a10 = *(const ull*)(A2s + ((((e2l + 1) << 6) + d0) << 1));
            ull a11 = *(const ull*)(A2s + ((((e2l + 1) << 6) + d1) << 1));
#pragma unroll
            for (int u = 0; u < 8; u++) {
                ulonglong2 hv = *(const ulonglong2*)(Hh + ((r0 + u) << 7) + (e2l << 1));
                sA[u] = fma2(hv.x, a00, sA[u]);
                sB[u] = fma2(hv.x, a01, sB[u]);
                sA[u] = fma2(hv.y, a10, sA[u]);
                sB[u] = fma2(hv.y, a11, sB[u]);
            }
        }
        __syncthreads();
    }

    // ---- Phase 3 epilogue: SIM (aliases T) ----
    {
        float b0 = ab2[d0], b1 = ab2[d1];
#pragma unroll
        for (int u = 0; u < 8; u++) {
            int r = r0 + u;
            float2 fa = up2(sA[u]);
            float2 fb = up2(sB[u]);
            T[r * 64 + d0] = fa.x + fa.y + b0;
            T[r * 64 + d1] = fb.x + fb.y + b1;
        }
    }
    __syncthreads();

    // ---- Phase 4: softmax over K neighbors + weighted sum of VG ----
    {
        int qq = tid >> 6, d = tid & 63;
        int base = qq * K;
        float m = -3.4e38f;
#pragma unroll
        for (int kk = 0; kk < K; kk++) m = fmaxf(m, T[(base + kk) * 64 + d]);
        float s = 0.f, agg = 0.f;
#pragma unroll
        for (int kk = 0; kk < K; kk++) {
            float wv = __expf(T[(base + kk) * 64 + d] - m);
            s += wv;
            agg += wv * VG[(base + kk) * 64 + d];
        }
        out[(ib + qq) * 64 + d] = agg / s;
    }
}

// ---------------------------------------------------------------------------
extern "C" void kernel_launch(void* const* d_in, const int* in_sizes, int n_in,
                              void* d_out, int out_size) {
    const float* x   = (const float*)d_in[0];
    const float* pos = (const float*)d_in[1];
    const float* Wq  = (const float*)d_in[2];
    const float* Wk  = (const float*)d_in[3];
    const float* Wv  = (const float*)d_in[4];
    const float* P1  = (const float*)d_in[5];
    const float* pb1 = (const float*)d_in[6];
    const float* P2  = (const float*)d_in[7];
    const float* pb2 = (const float*)d_in[8];
    const float* A1  = (const float*)d_in[9];
    const float* ab1 = (const float*)d_in[10];
    const float* A2  = (const float*)d_in[11];
    const float* ab2 = (const float*)d_in[12];
    float* out = (float*)d_out;

    cudaFuncSetAttribute(fused_kernel, cudaFuncAttributeMaxDynamicSharedMemorySize,
                         SMEM_FLOATS * sizeof(float));
    fused_kernel<<<GRID, NT, SMEM_FLOATS * sizeof(float)>>>(
        x, pos, Wq, Wk, Wv, P1, pb1, P2, pb2, A1, ab1, A2, ab2, out);
}

// round 10
// speedup vs baseline: 1.3792x; 1.3333x over previous
#include <cuda_runtime.h>
#include <cuda_bf16.h>
#include <math.h>
#include <stdint.h>

#define NPTS 1024
#define DIM  64
#define HID  256
#define K    16
#define QB   8
#define RB   128
#define GRID 128
#define NT   512
#define SK   72          // bf16 row stride for all MMA tiles (conflict-free ldmatrix)

__device__ float g_k[NPTS * DIM];
__device__ float g_v[NPTS * DIM];
__device__ unsigned g_bar;   // advances by GRID per launch

// ---- dynamic smem byte offsets ----
#define VG_OFF  0u          // 32768: fp32 VG[128][64]
#define TA_HI   32768u      // 18432: bf16 T hi [128][SK]
#define TA_LO   51200u      // 18432
#define A1_HI   69632u      // 36864: bf16 A1^T hi [256n][SK]
#define A1_LO   106496u     // 36864
#define A2C_HI  143360u     // 9216:  bf16 A2c^T hi [64n][SK]
#define A2C_LO  152576u     // 9216
#define HC_HI   161792u     // 18432: bf16 H-chunk hi [128][SK]
#define HC_LO   180224u     // 18432
#define SMEM_BYTES 198656u
// prolog aliases
#define PS_OFF  HC_HI       // pos staging (12288)
#define E_OFF   HC_HI       // E fp32 128x64 (32768)
#define P2I_OFF A2C_HI      // P2 interleaved fp32 (16384, spans A2C_HI+LO)

// ---------------- helpers ----------------
__device__ __forceinline__ uint32_t smem_u32(const void* p) {
    uint32_t a;
    asm("{ .reg .u64 t; cvta.to.shared.u64 t, %1; cvt.u32.u64 %0, t; }" : "=r"(a) : "l"(p));
    return a;
}
__device__ __forceinline__ void bf16split(float v, unsigned short& hb, unsigned short& lb) {
    __nv_bfloat16 h = __float2bfloat16(v);
    hb = __bfloat16_as_ushort(h);
    __nv_bfloat16 l = __float2bfloat16(v - __bfloat162float(h));
    lb = __bfloat16_as_ushort(l);
}
__device__ __forceinline__ void ldsm4(uint32_t& r0, uint32_t& r1, uint32_t& r2, uint32_t& r3,
                                      uint32_t addr) {
    asm volatile("ldmatrix.sync.aligned.m8n8.x4.shared.b16 {%0,%1,%2,%3}, [%4];"
                 : "=r"(r0), "=r"(r1), "=r"(r2), "=r"(r3) : "r"(addr));
}
__device__ __forceinline__ void mma_bf16(float* c, const uint32_t* a, const uint32_t* b) {
    asm volatile("mma.sync.aligned.m16n8k16.row.col.f32.bf16.bf16.f32 "
                 "{%0,%1,%2,%3},{%4,%5,%6,%7},{%8,%9},{%0,%1,%2,%3};"
                 : "+f"(c[0]), "+f"(c[1]), "+f"(c[2]), "+f"(c[3])
                 : "r"(a[0]), "r"(a[1]), "r"(a[2]), "r"(a[3]), "r"(b[0]), "r"(b[1]));
}
// A-operand lane address: 16x16 tile at (r0, k0), mats: (r0,k0),(r0+8,k0),(r0,k0+8),(r0+8,k0+8)
__device__ __forceinline__ uint32_t a_addr(uint32_t base, int r0, int k0, int lane) {
    int row = r0 + (lane & 7) + ((lane >> 3) & 1) * 8;
    int col = k0 + (lane >> 4) * 8;
    return base + (uint32_t)(row * SK + col) * 2u;
}
// B-operand pair lane address: two n-frags (nfA=nfb, nfB=nfb+1) x k16 at (n0, k0)
__device__ __forceinline__ uint32_t b_addr(uint32_t base, int n0, int nfb, int k0, int lane) {
    int g = lane >> 3;
    int row = n0 + (nfb + (g >> 1)) * 8 + (lane & 7);
    int col = k0 + (g & 1) * 8;
    return base + (uint32_t)(row * SK + col) * 2u;
}

// ---------------------------------------------------------------------------
__global__ __launch_bounds__(NT)
void fused_kernel(const float* __restrict__ x,
                  const float* __restrict__ pos,
                  const float* __restrict__ Wq,
                  const float* __restrict__ Wk,
                  const float* __restrict__ Wv,
                  const float* __restrict__ P1, const float* __restrict__ pb1,
                  const float* __restrict__ P2, const float* __restrict__ pb2,
                  const float* __restrict__ A1, const float* __restrict__ ab1,
                  const float* __restrict__ A2, const float* __restrict__ ab2,
                  float* __restrict__ out) {
    extern __shared__ char smc[];
    float* VG  = (float*)(smc + VG_OFF);
    float* ps  = (float*)(smc + PS_OFF);
    float* E   = (float*)(smc + E_OFF);
    float* P2i = (float*)(smc + P2I_OFF);

    __shared__ int   nb[RB];
    __shared__ float rp[RB][3];
    __shared__ float qrow[QB * DIM];
    __shared__ float xs[QB * DIM];
    __shared__ float cval[QB][2][K];
    __shared__ int   cidx[QB][2][K];
    __shared__ unsigned s_ticket;

    int tid = threadIdx.x;
    int ib = blockIdx.x * QB;
    int w = tid >> 5, lane = tid & 31;
    uint32_t sb = smem_u32(smc);

    // ---- Prolog staging: pos, x rows, P2 interleaved, A1 full (bf16 hi/lo) ----
    for (int t = tid; t < NPTS * 3; t += NT) ps[t] = pos[t];
    for (int t = tid; t < QB * DIM; t += NT) xs[t] = x[ib * DIM + t];
    for (int t = tid; t < 4096; t += NT) {
        int s = t & 1, d = (t >> 1) & 63, h2 = t >> 7;
        P2i[t] = P2[(2 * h2 + s) * DIM + d];
    }
    for (int t = tid; t < HID * DIM; t += NT) {     // 16384
        int n = t & 255, kd = t >> 8;
        float v = A1[kd * HID + n];
        unsigned short hh, ll; bf16split(v, hh, ll);
        uint32_t so = (uint32_t)(n * SK + kd) * 2u;
        *(unsigned short*)(smc + A1_HI + so) = hh;
        *(unsigned short*)(smc + A1_LO + so) = ll;
    }
    __syncthreads();

    // ---- qkv for this block's 8 rows ----
    {
        int r = tid >> 6, d = tid & 63;
        float q = 0.f, kk = 0.f, vv = 0.f;
#pragma unroll 4
        for (int c = 0; c < DIM; c++) {
            float xv = xs[r * DIM + c];
            q  += xv * Wq[c * DIM + d];
            kk += xv * Wk[c * DIM + d];
            vv += xv * Wv[c * DIM + d];
        }
        qrow[r * DIM + d] = q;
        g_k[(ib + r) * DIM + d] = kk;
        g_v[(ib + r) * DIM + d] = vv;
    }
    __syncthreads();
    if (tid == 0) {
        __threadfence();
        s_ticket = atomicAdd(&g_bar, 1u);
    }

    // ---- kNN: 2 warps per query, 512 candidates each ----
    {
        int qq = w >> 1, hh = w & 1;
        int gi = ib + qq;
        float px = ps[gi * 3 + 0], py = ps[gi * 3 + 1], pz = ps[gi * 3 + 2];
        float v[16]; int id[16];
#pragma unroll
        for (int c = 0; c < 16; c++) {
            int j = hh * 512 + c * 32 + lane;
            float dx = px - ps[j * 3 + 0];
            float dy = py - ps[j * 3 + 1];
            float dz = pz - ps[j * 3 + 2];
            v[c] = dx * dx + dy * dy + dz * dz;
            id[c] = j;
        }
        for (int r = 0; r < K; r++) {
            float bv = v[0]; int bi = id[0];
#pragma unroll
            for (int c = 1; c < 16; c++)
                if (v[c] < bv || (v[c] == bv && id[c] < bi)) { bv = v[c]; bi = id[c]; }
#pragma unroll
            for (int off = 16; off > 0; off >>= 1) {
                float ov = __shfl_down_sync(0xffffffffu, bv, off);
                int   oi = __shfl_down_sync(0xffffffffu, bi, off);
                if (ov < bv || (ov == bv && oi < bi)) { bv = ov; bi = oi; }
            }
            bv = __shfl_sync(0xffffffffu, bv, 0);
            bi = __shfl_sync(0xffffffffu, bi, 0);
            if (lane == 0) { cval[qq][hh][r] = bv; cidx[qq][hh][r] = bi; }
#pragma unroll
            for (int c = 0; c < 16; c++) if (id[c] == bi) v[c] = 3.4e38f;
        }
    }
    __syncthreads();
    if ((w & 1) == 0) {
        int qq = w >> 1;
        float mv = cval[qq][lane >> 4][lane & 15];
        int   mi = cidx[qq][lane >> 4][lane & 15];
        for (int r = 0; r < K; r++) {
            float bv = mv; int bi = mi;
#pragma unroll
            for (int off = 16; off > 0; off >>= 1) {
                float ov = __shfl_down_sync(0xffffffffu, bv, off);
                int   oi = __shfl_down_sync(0xffffffffu, bi, off);
                if (ov < bv || (ov == bv && oi < bi)) { bv = ov; bi = oi; }
            }
            bi = __shfl_sync(0xffffffffu, bi, 0);
            if (lane == 0) nb[qq * K + r] = bi;
            if (mi == bi) mv = 3.4e38f;
        }
    }
    __syncthreads();

    for (int t = tid; t < RB * 3; t += NT) {
        int r = t / 3, c = t - r * 3;
        int gi = ib + (r >> 4);
        rp[r][c] = ps[gi * 3 + c] - ps[nb[r] * 3 + c];
    }
    __syncthreads();

    // ---- Phase 1a: E = relu(rp @ P1 + pb1)  (overwrites ps) ----
    for (int t = tid; t < RB * 64; t += NT) {
        int r = t >> 6, h = t & 63;
        float e = rp[r][0] * P1[h] + rp[r][1] * P1[64 + h]
                + rp[r][2] * P1[128 + h] + pb1[h];
        E[t] = fmaxf(e, 0.f);
    }
    if (tid == 0) {
        unsigned target = (s_ticket / GRID + 1u) * GRID;
        while ((int)(*(volatile unsigned*)&g_bar - target) < 0) { }
        __threadfence();
    }
    __syncthreads();

    // ---- Phase 1b: rpe = E @ P2 + pb2 ; T(bf16 split) ; VG ----
    {
        int r0b = w * 8;
        int d0 = lane, d1 = lane + 32;
        float aA0[8], aA1[8], aB0[8], aB1[8];
#pragma unroll
        for (int u = 0; u < 8; u++) { aA0[u] = aA1[u] = aB0[u] = aB1[u] = 0.f; }
#pragma unroll 4
        for (int h2 = 0; h2 < 32; h2++) {
            float2 p0 = *(const float2*)(P2i + (((h2 << 6) + d0) << 1));
            float2 p1 = *(const float2*)(P2i + (((h2 << 6) + d1) << 1));
#pragma unroll
            for (int u = 0; u < 8; u++) {
                float2 ev = *(const float2*)(E + ((r0b + u) << 6) + (h2 << 1));
                aA0[u] += ev.x * p0.x; aA1[u] += ev.y * p0.y;
                aB0[u] += ev.x * p1.x; aB1[u] += ev.y * p1.y;
            }
        }
        float b0 = pb2[d0], b1 = pb2[d1];
#pragma unroll
        for (int u = 0; u < 8; u++) {
            int r = r0b + u;
            int j = nb[r];
            int qq = r >> 4;
            float rpe0 = aA0[u] + aA1[u] + b0;
            float rpe1 = aB0[u] + aB1[u] + b1;
            float t0 = qrow[qq * 64 + d0] - g_k[j * 64 + d0] + rpe0;
            float t1 = qrow[qq * 64 + d1] - g_k[j * 64 + d1] + rpe1;
            VG[r * 64 + d0] = g_v[j * 64 + d0] + rpe0;
            VG[r * 64 + d1] = g_v[j * 64 + d1] + rpe1;
            unsigned short h0, l0, h1, l1;
            bf16split(t0, h0, l0);
            bf16split(t1, h1, l1);
            uint32_t so0 = (uint32_t)(r * SK + d0) * 2u;
            uint32_t so1 = (uint32_t)(r * SK + d1) * 2u;
            *(unsigned short*)(smc + TA_HI + so0) = h0;
            *(unsigned short*)(smc + TA_LO + so0) = l0;
            *(unsigned short*)(smc + TA_HI + so1) = h1;
            *(unsigned short*)(smc + TA_LO + so1) = l1;
        }
    }
    __syncthreads();

    // ---- Chunked MMA: phases 2+3 over 4 chunks of 64 HID cols ----
    int r0 = (w & 7) * 16;           // query row-tile
    int n0w = (w >> 3) * 32;         // 32-col half (chunk-local for p2, DIM for p3)
    float C3[16];
#pragma unroll
    for (int i = 0; i < 16; i++) C3[i] = 0.f;

    for (int chunk = 0; chunk < 4; chunk++) {
        // stage A2 chunk (overwrites P2i on chunk 0 — fine, phase 1b done)
        for (int t = tid; t < 4096; t += NT) {
            int n = t & 63, kk = t >> 6;
            float v = A2[(chunk * 64 + kk) * DIM + n];
            unsigned short hh, ll; bf16split(v, hh, ll);
            uint32_t so = (uint32_t)(n * SK + kk) * 2u;
            *(unsigned short*)(smc + A2C_HI + so) = hh;
            *(unsigned short*)(smc + A2C_LO + so) = ll;
        }

        // ---- Phase 2: C2 = T @ A1[:, chunk cols n0w..n0w+32) ----
        float C2[16];
#pragma unroll
        for (int i = 0; i < 16; i++) C2[i] = 0.f;
        int bn0 = chunk * 64 + n0w;      // row base in A1 staged [n][k]
#pragma unroll
        for (int ks = 0; ks < 4; ks++) {
            int k0 = ks * 16;
            uint32_t ah[4], al[4];
            ldsm4(ah[0], ah[1], ah[2], ah[3], a_addr(sb + TA_HI, r0, k0, lane));
            ldsm4(al[0], al[1], al[2], al[3], a_addr(sb + TA_LO, r0, k0, lane));
#pragma unroll
            for (int nfp = 0; nfp < 2; nfp++) {
                uint32_t bh[4], bl[4];
                ldsm4(bh[0], bh[1], bh[2], bh[3], b_addr(sb + A1_HI, bn0, nfp * 2, k0, lane));
                ldsm4(bl[0], bl[1], bl[2], bl[3], b_addr(sb + A1_LO, bn0, nfp * 2, k0, lane));
                mma_bf16(C2 + nfp * 8,     ah, bh);
                mma_bf16(C2 + nfp * 8,     ah, bl);
                mma_bf16(C2 + nfp * 8,     al, bh);
                mma_bf16(C2 + nfp * 8 + 4, ah, bh + 2);
                mma_bf16(C2 + nfp * 8 + 4, ah, bl + 2);
                mma_bf16(C2 + nfp * 8 + 4, al, bh + 2);
            }
        }
        __syncthreads();   // prior-chunk phase-3 H reads done; A2c staged

        // bias + relu + bf16 split -> H chunk
        {
            int rowA = r0 + (lane >> 2);
            int cbase = n0w + 2 * (lane & 3);
#pragma unroll
            for (int nf = 0; nf < 4; nf++) {
                int cl = cbase + nf * 8;               // chunk-local col
                float2 bias = *(const float2*)(ab1 + chunk * 64 + cl);
                float v00 = fmaxf(C2[nf * 4 + 0] + bias.x, 0.f);
                float v01 = fmaxf(C2[nf * 4 + 1] + bias.y, 0.f);
                float v10 = fmaxf(C2[nf * 4 + 2] + bias.x, 0.f);
                float v11 = fmaxf(C2[nf * 4 + 3] + bias.y, 0.f);
                unsigned short h00, l00, h01, l01, h10, l10, h11, l11;
                bf16split(v00, h00, l00); bf16split(v01, h01, l01);
                bf16split(v10, h10, l10); bf16split(v11, h11, l11);
                uint32_t soA = (uint32_t)(rowA * SK + cl) * 2u;
                uint32_t soB = (uint32_t)((rowA + 8) * SK + cl) * 2u;
                *(uint32_t*)(smc + HC_HI + soA) = (uint32_t)h00 | ((uint32_t)h01 << 16);
                *(uint32_t*)(smc + HC_LO + soA) = (uint32_t)l00 | ((uint32_t)l01 << 16);
                *(uint32_t*)(smc + HC_HI + soB) = (uint32_t)h10 | ((uint32_t)h11 << 16);
                *(uint32_t*)(smc + HC_LO + soB) = (uint32_t)l10 | ((uint32_t)l11 << 16);
            }
        }
        __syncthreads();

        // ---- Phase 3: C3 += H_chunk @ A2_chunk ----
#pragma unroll
        for (int ks = 0; ks < 4; ks++) {
            int k0 = ks * 16;
            uint32_t ah[4], al[4];
            ldsm4(ah[0], ah[1], ah[2], ah[3], a_addr(sb + HC_HI, r0, k0, lane));
            ldsm4(al[0], al[1], al[2], al[3], a_addr(sb + HC_LO, r0, k0, lane));
#pragma unroll
            for (int nfp = 0; nfp < 2; nfp++) {
                uint32_t bh[4], bl[4];
                ldsm4(bh[0], bh[1], bh[2], bh[3], b_addr(sb + A2C_HI, n0w, nfp * 2, k0, lane));
                ldsm4(bl[0], bl[1], bl[2], bl[3], b_addr(sb + A2C_LO, n0w, nfp * 2, k0, lane));
                mma_bf16(C3 + nfp * 8,     ah, bh);
                mma_bf16(C3 + nfp * 8,     ah, bl);
                mma_bf16(C3 + nfp * 8,     al, bh);
                mma_bf16(C3 + nfp * 8 + 4, ah, bh + 2);
                mma_bf16(C3 + nfp * 8 + 4, ah, bl + 2);
                mma_bf16(C3 + nfp * 8 + 4, al, bh + 2);
            }
        }
        __syncthreads();   // before restaging A2c / rewriting H next chunk
    }

    // ---- Phase 4: softmax over 16 neighbors (register fragments + shfl) ----
    {
        int q = w & 7;
        int rowA = r0 + (lane >> 2);
#pragma unroll
        for (int nf = 0; nf < 4; nf++) {
            int c = n0w + nf * 8 + 2 * (lane & 3);
            float2 b2 = *(const float2*)(ab2 + c);
            float s00 = C3[nf * 4 + 0] + b2.x;
            float s01 = C3[nf * 4 + 1] + b2.y;
            float s10 = C3[nf * 4 + 2] + b2.x;
            float s11 = C3[nf * 4 + 3] + b2.y;
            float m0 = fmaxf(s00, s10);
            float m1 = fmaxf(s01, s11);
#pragma unroll
            for (int msk = 4; msk <= 16; msk <<= 1) {
                m0 = fmaxf(m0, __shfl_xor_sync(0xffffffffu, m0, msk));
                m1 = fmaxf(m1, __shfl_xor_sync(0xffffffffu, m1, msk));
            }
            float e00 = __expf(s00 - m0), e10 = __expf(s10 - m0);
            float e01 = __expf(s01 - m1), e11 = __expf(s11 - m1);
            float2 vgA = *(const float2*)(VG + rowA * 64 + c);
            float2 vgB = *(const float2*)(VG + (rowA + 8) * 64 + c);
            float sum0 = e00 + e10, sum1 = e01 + e11;
            float agg0 = e00 * vgA.x + e10 * vgB.x;
            float agg1 = e01 * vgA.y + e11 * vgB.y;
#pragma unroll
            for (int msk = 4; msk <= 16; msk <<= 1) {
                sum0 += __shfl_xor_sync(0xffffffffu, sum0, msk);
                sum1 += __shfl_xor_sync(0xffffffffu, sum1, msk);
                agg0 += __shfl_xor_sync(0xffffffffu, agg0, msk);
                agg1 += __shfl_xor_sync(0xffffffffu, agg1, msk);
            }
            if (lane < 4) {
                float2 o = make_float2(agg0 / sum0, agg1 / sum1);
                *(float2*)(out + (ib + q) * 64 + c) = o;
            }
        }
    }
}

// ---------------------------------------------------------------------------
extern "C" void kernel_launch(void* const* d_in, const int* in_sizes, int n_in,
                              void* d_out, int out_size) {
    const float* x   = (const float*)d_in[0];
    const float* pos = (const float*)d_in[1];
    const float* Wq  = (const float*)d_in[2];
    const float* Wk  = (const float*)d_in[3];
    const float* Wv  = (const float*)d_in[4];
    const float* P1  = (const float*)d_in[5];
    const float* pb1 = (const float*)d_in[6];
    const float* P2  = (const float*)d_in[7];
    const float* pb2 = (const float*)d_in[8];
    const float* A1  = (const float*)d_in[9];
    const float* ab1 = (const float*)d_in[10];
    const float* A2  = (const float*)d_in[11];
    const float* ab2 = (const float*)d_in[12];
    float* out = (float*)d_out;

    cudaFuncSetAttribute(fused_kernel, cudaFuncAttributeMaxDynamicSharedMemorySize,
                         SMEM_BYTES);
    fused_kernel<<<GRID, NT, SMEM_BYTES>>>(
        x, pos, Wq, Wk, Wv, P1, pb1, P2, pb2, A1, ab1, A2, ab2, out);
}

// round 11
// speedup vs baseline: 1.4329x; 1.0389x over previous
#include <cuda_runtime.h>
#include <cuda_bf16.h>
#include <math.h>
#include <stdint.h>

#define NPTS 1024
#define DIM  64
#define HID  256
#define K    16
#define QB   8
#define RB   128
#define GRID 128
#define NT   512
#define SK   72          // bf16 row stride for all MMA tiles (conflict-free ldmatrix)

__device__ float g_k[NPTS * DIM];
__device__ float g_v[NPTS * DIM];
__device__ unsigned g_bar;   // advances by GRID per launch

// ---- dynamic smem byte offsets ----
#define VG_OFF  0u          // 32768: fp32 VG[128][64]
#define TA_HI   32768u      // 18432: bf16 T hi [128][SK]
#define TA_LO   51200u      // 18432
#define A1_HI   69632u      // 36864: bf16 A1^T hi [256n][SK]
#define A1_LO   106496u     // 36864
#define A2C_HI  143360u     // 9216:  bf16 A2c^T / P2^T hi [64n][SK]
#define A2C_LO  152576u     // 9216
#define HC_HI   161792u     // 18432: bf16 H-chunk / E hi [128][SK]
#define HC_LO   180224u     // 18432
#define SMEM_BYTES 198656u
// prolog aliases
#define PS_OFF  HC_HI       // pos staging (12288)

// ---------------- helpers ----------------
__device__ __forceinline__ uint32_t smem_u32(const void* p) {
    uint32_t a;
    asm("{ .reg .u64 t; cvta.to.shared.u64 t, %1; cvt.u32.u64 %0, t; }" : "=r"(a) : "l"(p));
    return a;
}
__device__ __forceinline__ void bf16split(float v, unsigned short& hb, unsigned short& lb) {
    __nv_bfloat16 h = __float2bfloat16(v);
    hb = __bfloat16_as_ushort(h);
    __nv_bfloat16 l = __float2bfloat16(v - __bfloat162float(h));
    lb = __bfloat16_as_ushort(l);
}
__device__ __forceinline__ void ldsm4(uint32_t& r0, uint32_t& r1, uint32_t& r2, uint32_t& r3,
                                      uint32_t addr) {
    asm volatile("ldmatrix.sync.aligned.m8n8.x4.shared.b16 {%0,%1,%2,%3}, [%4];"
                 : "=r"(r0), "=r"(r1), "=r"(r2), "=r"(r3) : "r"(addr));
}
__device__ __forceinline__ void mma_bf16(float* c, const uint32_t* a, const uint32_t* b) {
    asm volatile("mma.sync.aligned.m16n8k16.row.col.f32.bf16.bf16.f32 "
                 "{%0,%1,%2,%3},{%4,%5,%6,%7},{%8,%9},{%0,%1,%2,%3};"
                 : "+f"(c[0]), "+f"(c[1]), "+f"(c[2]), "+f"(c[3])
                 : "r"(a[0]), "r"(a[1]), "r"(a[2]), "r"(a[3]), "r"(b[0]), "r"(b[1]));
}
__device__ __forceinline__ uint32_t a_addr(uint32_t base, int r0, int k0, int lane) {
    int row = r0 + (lane & 7) + ((lane >> 3) & 1) * 8;
    int col = k0 + (lane >> 4) * 8;
    return base + (uint32_t)(row * SK + col) * 2u;
}
__device__ __forceinline__ uint32_t b_addr(uint32_t base, int n0, int nfb, int k0, int lane) {
    int g = lane >> 3;
    int row = n0 + (nfb + (g >> 1)) * 8 + (lane & 7);
    int col = k0 + (g & 1) * 8;
    return base + (uint32_t)(row * SK + col) * 2u;
}

// ---------------------------------------------------------------------------
__global__ __launch_bounds__(NT)
void fused_kernel(const float* __restrict__ x,
                  const float* __restrict__ pos,
                  const float* __restrict__ Wq,
                  const float* __restrict__ Wk,
                  const float* __restrict__ Wv,
                  const float* __restrict__ P1, const float* __restrict__ pb1,
                  const float* __restrict__ P2, const float* __restrict__ pb2,
                  const float* __restrict__ A1, const float* __restrict__ ab1,
                  const float* __restrict__ A2, const float* __restrict__ ab2,
                  float* __restrict__ out) {
    extern __shared__ char smc[];
    float* VG  = (float*)(smc + VG_OFF);
    float* ps  = (float*)(smc + PS_OFF);

    __shared__ int   nb[RB];
    __shared__ float rp[RB][3];
    __shared__ float qrow[QB * DIM];
    __shared__ float xs[QB * DIM];
    __shared__ float cval[QB][2][K];
    __shared__ int   cidx[QB][2][K];
    __shared__ unsigned s_ticket;

    int tid = threadIdx.x;
    int ib = blockIdx.x * QB;
    int w = tid >> 5, lane = tid & 31;
    uint32_t sb = smem_u32(smc);

    // ---- Prolog staging: pos, x rows, P2^T (bf16 split), A1 full (bf16 split) ----
    for (int t = tid; t < NPTS * 3; t += NT) ps[t] = pos[t];
    for (int t = tid; t < QB * DIM; t += NT) xs[t] = x[ib * DIM + t];
    for (int t = tid; t < 4096; t += NT) {          // P2^T into A2C region
        int n = t & 63, kk = t >> 6;
        float v = P2[kk * 64 + n];
        unsigned short hh, ll; bf16split(v, hh, ll);
        uint32_t so = (uint32_t)(n * SK + kk) * 2u;
        *(unsigned short*)(smc + A2C_HI + so) = hh;
        *(unsigned short*)(smc + A2C_LO + so) = ll;
    }
    for (int t = tid; t < HID * DIM; t += NT) {     // A1^T full
        int n = t & 255, kd = t >> 8;
        float v = A1[kd * HID + n];
        unsigned short hh, ll; bf16split(v, hh, ll);
        uint32_t so = (uint32_t)(n * SK + kd) * 2u;
        *(unsigned short*)(smc + A1_HI + so) = hh;
        *(unsigned short*)(smc + A1_LO + so) = ll;
    }
    __syncthreads();

    // ---- qkv for this block's 8 rows ----
    {
        int r = tid >> 6, d = tid & 63;
        float q = 0.f, kk = 0.f, vv = 0.f;
#pragma unroll 4
        for (int c = 0; c < DIM; c++) {
            float xv = xs[r * DIM + c];
            q  += xv * Wq[c * DIM + d];
            kk += xv * Wk[c * DIM + d];
            vv += xv * Wv[c * DIM + d];
        }
        qrow[r * DIM + d] = q;
        g_k[(ib + r) * DIM + d] = kk;
        g_v[(ib + r) * DIM + d] = vv;
    }
    __syncthreads();
    if (tid == 0) {
        __threadfence();
        s_ticket = atomicAdd(&g_bar, 1u);
    }

    // ---- kNN: 2 warps per query, 512 candidates each ----
    {
        int qq = w >> 1, hh = w & 1;
        int gi = ib + qq;
        float px = ps[gi * 3 + 0], py = ps[gi * 3 + 1], pz = ps[gi * 3 + 2];
        float v[16]; int id[16];
#pragma unroll
        for (int c = 0; c < 16; c++) {
            int j = hh * 512 + c * 32 + lane;
            float dx = px - ps[j * 3 + 0];
            float dy = py - ps[j * 3 + 1];
            float dz = pz - ps[j * 3 + 2];
            v[c] = dx * dx + dy * dy + dz * dz;
            id[c] = j;
        }
        for (int r = 0; r < K; r++) {
            float bv = v[0]; int bi = id[0];
#pragma unroll
            for (int c = 1; c < 16; c++)
                if (v[c] < bv || (v[c] == bv && id[c] < bi)) { bv = v[c]; bi = id[c]; }
#pragma unroll
            for (int off = 16; off > 0; off >>= 1) {
                float ov = __shfl_down_sync(0xffffffffu, bv, off);
                int   oi = __shfl_down_sync(0xffffffffu, bi, off);
                if (ov < bv || (ov == bv && oi < bi)) { bv = ov; bi = oi; }
            }
            bv = __shfl_sync(0xffffffffu, bv, 0);
            bi = __shfl_sync(0xffffffffu, bi, 0);
            if (lane == 0) { cval[qq][hh][r] = bv; cidx[qq][hh][r] = bi; }
#pragma unroll
            for (int c = 0; c < 16; c++) if (id[c] == bi) v[c] = 3.4e38f;
        }
    }
    __syncthreads();
    if ((w & 1) == 0) {
        int qq = w >> 1;
        float mv = cval[qq][lane >> 4][lane & 15];
        int   mi = cidx[qq][lane >> 4][lane & 15];
        for (int r = 0; r < K; r++) {
            float bv = mv; int bi = mi;
#pragma unroll
            for (int off = 16; off > 0; off >>= 1) {
                float ov = __shfl_down_sync(0xffffffffu, bv, off);
                int   oi = __shfl_down_sync(0xffffffffu, bi, off);
                if (ov < bv || (ov == bv && oi < bi)) { bv = ov; bi = oi; }
            }
            bi = __shfl_sync(0xffffffffu, bi, 0);
            if (lane == 0) nb[qq * K + r] = bi;
            if (mi == bi) mv = 3.4e38f;
        }
    }
    __syncthreads();

    for (int t = tid; t < RB * 3; t += NT) {
        int r = t / 3, c = t - r * 3;
        int gi = ib + (r >> 4);
        rp[r][c] = ps[gi * 3 + c] - ps[nb[r] * 3 + c];
    }
    __syncthreads();

    // ---- Phase 1a: E = relu(rp @ P1 + pb1), written as bf16 split tiles
    //      (overwrites ps in the HC region) ----
    for (int t = tid; t < RB * 64; t += NT) {
        int r = t >> 6, h = t & 63;
        float e = rp[r][0] * P1[h] + rp[r][1] * P1[64 + h]
                + rp[r][2] * P1[128 + h] + pb1[h];
        e = fmaxf(e, 0.f);
        unsigned short hh, ll; bf16split(e, hh, ll);
        uint32_t so = (uint32_t)(r * SK + h) * 2u;
        *(unsigned short*)(smc + HC_HI + so) = hh;
        *(unsigned short*)(smc + HC_LO + so) = ll;
    }
    if (tid == 0) {     // global barrier: all blocks' k/v visible before gather
        unsigned target = (s_ticket / GRID + 1u) * GRID;
        while ((int)(*(volatile unsigned*)&g_bar - target) < 0) { }
        __threadfence();
    }
    __syncthreads();

    int r0 = (w & 7) * 16;           // query row-tile (16 rows = one query)
    int n0w = (w >> 3) * 32;         // 32-col half
    int rowA = r0 + (lane >> 2);
    int rowB = rowA + 8;

    // ---- Phase 1b (MMA): rpe = E @ P2 ; T(bf16 split) ; VG ----
    {
        float C1[16];
#pragma unroll
        for (int i = 0; i < 16; i++) C1[i] = 0.f;
#pragma unroll
        for (int ks = 0; ks < 4; ks++) {
            int k0 = ks * 16;
            uint32_t ah[4], al[4];
            ldsm4(ah[0], ah[1], ah[2], ah[3], a_addr(sb + HC_HI, r0, k0, lane));
            ldsm4(al[0], al[1], al[2], al[3], a_addr(sb + HC_LO, r0, k0, lane));
#pragma unroll
            for (int nfp = 0; nfp < 2; nfp++) {
                uint32_t bh[4], bl[4];
                ldsm4(bh[0], bh[1], bh[2], bh[3], b_addr(sb + A2C_HI, n0w, nfp * 2, k0, lane));
                ldsm4(bl[0], bl[1], bl[2], bl[3], b_addr(sb + A2C_LO, n0w, nfp * 2, k0, lane));
                mma_bf16(C1 + nfp * 8,     ah, bh);
                mma_bf16(C1 + nfp * 8,     ah, bl);
                mma_bf16(C1 + nfp * 8,     al, bh);
                mma_bf16(C1 + nfp * 8 + 4, ah, bh + 2);
                mma_bf16(C1 + nfp * 8 + 4, ah, bl + 2);
                mma_bf16(C1 + nfp * 8 + 4, al, bh + 2);
            }
        }
        // epilogue: T = q - k + rpe (split to TA), VG = v + rpe
        int qq = w & 7;
        int j0 = nb[rowA], j1 = nb[rowB];
#pragma unroll
        for (int nf = 0; nf < 4; nf++) {
            int c = n0w + nf * 8 + 2 * (lane & 3);
            float2 b2 = *(const float2*)(pb2 + c);
            float2 qv = *(const float2*)(qrow + qq * 64 + c);
            float2 k0v = *(const float2*)(g_k + j0 * 64 + c);
            float2 k1v = *(const float2*)(g_k + j1 * 64 + c);
            float2 v0v = *(const float2*)(g_v + j0 * 64 + c);
            float2 v1v = *(const float2*)(g_v + j1 * 64 + c);
            float rpe00 = C1[nf * 4 + 0] + b2.x, rpe01 = C1[nf * 4 + 1] + b2.y;
            float rpe10 = C1[nf * 4 + 2] + b2.x, rpe11 = C1[nf * 4 + 3] + b2.y;
            *(float2*)(VG + rowA * 64 + c) = make_float2(v0v.x + rpe00, v0v.y + rpe01);
            *(float2*)(VG + rowB * 64 + c) = make_float2(v1v.x + rpe10, v1v.y + rpe11);
            float t00 = qv.x - k0v.x + rpe00;
            float t01 = qv.y - k0v.y + rpe01;
            float t10 = qv.x - k1v.x + rpe10;
            float t11 = qv.y - k1v.y + rpe11;
            unsigned short h00, l00, h01, l01, h10, l10, h11, l11;
            bf16split(t00, h00, l00); bf16split(t01, h01, l01);
            bf16split(t10, h10, l10); bf16split(t11, h11, l11);
            uint32_t soA = (uint32_t)(rowA * SK + c) * 2u;
            uint32_t soB = (uint32_t)(rowB * SK + c) * 2u;
            *(uint32_t*)(smc + TA_HI + soA) = (uint32_t)h00 | ((uint32_t)h01 << 16);
            *(uint32_t*)(smc + TA_LO + soA) = (uint32_t)l00 | ((uint32_t)l01 << 16);
            *(uint32_t*)(smc + TA_HI + soB) = (uint32_t)h10 | ((uint32_t)h11 << 16);
            *(uint32_t*)(smc + TA_LO + soB) = (uint32_t)l10 | ((uint32_t)l11 << 16);
        }
    }
    __syncthreads();

    // ---- Chunked MMA: phases 2+3 over 4 chunks of 64 HID cols ----
    float C3[16];
#pragma unroll
    for (int i = 0; i < 16; i++) C3[i] = 0.f;

    for (int chunk = 0; chunk < 4; chunk++) {
        // stage A2 chunk (chunk 0 overwrites P2^T — phase 1b done)
        for (int t = tid; t < 4096; t += NT) {
            int n = t & 63, kk = t >> 6;
            float v = A2[(chunk * 64 + kk) * DIM + n];
            unsigned short hh, ll; bf16split(v, hh, ll);
            uint32_t so = (uint32_t)(n * SK + kk) * 2u;
            *(unsigned short*)(smc + A2C_HI + so) = hh;
            *(unsigned short*)(smc + A2C_LO + so) = ll;
        }

        // ---- Phase 2: C2 = T @ A1[:, chunk cols n0w..n0w+32) ----
        float C2[16];
#pragma unroll
        for (int i = 0; i < 16; i++) C2[i] = 0.f;
        int bn0 = chunk * 64 + n0w;
#pragma unroll
        for (int ks = 0; ks < 4; ks++) {
            int k0 = ks * 16;
            uint32_t ah[4], al[4];
            ldsm4(ah[0], ah[1], ah[2], ah[3], a_addr(sb + TA_HI, r0, k0, lane));
            ldsm4(al[0], al[1], al[2], al[3], a_addr(sb + TA_LO, r0, k0, lane));
#pragma unroll
            for (int nfp = 0; nfp < 2; nfp++) {
                uint32_t bh[4], bl[4];
                ldsm4(bh[0], bh[1], bh[2], bh[3], b_addr(sb + A1_HI, bn0, nfp * 2, k0, lane));
                ldsm4(bl[0], bl[1], bl[2], bl[3], b_addr(sb + A1_LO, bn0, nfp * 2, k0, lane));
                mma_bf16(C2 + nfp * 8,     ah, bh);
                mma_bf16(C2 + nfp * 8,     ah, bl);
                mma_bf16(C2 + nfp * 8,     al, bh);
                mma_bf16(C2 + nfp * 8 + 4, ah, bh + 2);
                mma_bf16(C2 + nfp * 8 + 4, ah, bl + 2);
                mma_bf16(C2 + nfp * 8 + 4, al, bh + 2);
            }
        }
        __syncthreads();   // prior-chunk H reads done; A2c staged

        // bias + relu + bf16 split -> H chunk
        {
            int cbase = n0w + 2 * (lane & 3);
#pragma unroll
            for (int nf = 0; nf < 4; nf++) {
                int cl = cbase + nf * 8;
                float2 bias = *(const float2*)(ab1 + chunk * 64 + cl);
                float v00 = fmaxf(C2[nf * 4 + 0] + bias.x, 0.f);
                float v01 = fmaxf(C2[nf * 4 + 1] + bias.y, 0.f);
                float v10 = fmaxf(C2[nf * 4 + 2] + bias.x, 0.f);
                float v11 = fmaxf(C2[nf * 4 + 3] + bias.y, 0.f);
                unsigned short h00, l00, h01, l01, h10, l10, h11, l11;
                bf16split(v00, h00, l00); bf16split(v01, h01, l01);
                bf16split(v10, h10, l10); bf16split(v11, h11, l11);
                uint32_t soA = (uint32_t)(rowA * SK + cl) * 2u;
                uint32_t soB = (uint32_t)(rowB * SK + cl) * 2u;
                *(uint32_t*)(smc + HC_HI + soA) = (uint32_t)h00 | ((uint32_t)h01 << 16);
                *(uint32_t*)(smc + HC_LO + soA) = (uint32_t)l00 | ((uint32_t)l01 << 16);
                *(uint32_t*)(smc + HC_HI + soB) = (uint32_t)h10 | ((uint32_t)h11 << 16);
                *(uint32_t*)(smc + HC_LO + soB) = (uint32_t)l10 | ((uint32_t)l11 << 16);
            }
        }
        __syncthreads();

        // ---- Phase 3: C3 += H_chunk @ A2_chunk ----
#pragma unroll
        for (int ks = 0; ks < 4; ks++) {
            int k0 = ks * 16;
            uint32_t ah[4], al[4];
            ldsm4(ah[0], ah[1], ah[2], ah[3], a_addr(sb + HC_HI, r0, k0, lane));
            ldsm4(al[0], al[1], al[2], al[3], a_addr(sb + HC_LO, r0, k0, lane));
#pragma unroll
            for (int nfp = 0; nfp < 2; nfp++) {
                uint32_t bh[4], bl[4];
                ldsm4(bh[0], bh[1], bh[2], bh[3], b_addr(sb + A2C_HI, n0w, nfp * 2, k0, lane));
                ldsm4(bl[0], bl[1], bl[2], bl[3], b_addr(sb + A2C_LO, n0w, nfp * 2, k0, lane));
                mma_bf16(C3 + nfp * 8,     ah, bh);
                mma_bf16(C3 + nfp * 8,     ah, bl);
                mma_bf16(C3 + nfp * 8,     al, bh);
                mma_bf16(C3 + nfp * 8 + 4, ah, bh + 2);
                mma_bf16(C3 + nfp * 8 + 4, ah, bl + 2);
                mma_bf16(C3 + nfp * 8 + 4, al, bh + 2);
            }
        }
        __syncthreads();   // before restaging A2c / rewriting H
    }

    // ---- Phase 4: softmax over 16 neighbors (register fragments + shfl) ----
    {
        int q = w & 7;
#pragma unroll
        for (int nf = 0; nf < 4; nf++) {
            int c = n0w + nf * 8 + 2 * (lane & 3);
            float2 b2 = *(const float2*)(ab2 + c);
            float s00 = C3[nf * 4 + 0] + b2.x;
            float s01 = C3[nf * 4 + 1] + b2.y;
            float s10 = C3[nf * 4 + 2] + b2.x;
            float s11 = C3[nf * 4 + 3] + b2.y;
            float m0 = fmaxf(s00, s10);
            float m1 = fmaxf(s01, s11);
#pragma unroll
            for (int msk = 4; msk <= 16; msk <<= 1) {
                m0 = fmaxf(m0, __shfl_xor_sync(0xffffffffu, m0, msk));
                m1 = fmaxf(m1, __shfl_xor_sync(0xffffffffu, m1, msk));
            }
            float e00 = __expf(s00 - m0), e10 = __expf(s10 - m0);
            float e01 = __expf(s01 - m1), e11 = __expf(s11 - m1);
            float2 vgA = *(const float2*)(VG + rowA * 64 + c);
            float2 vgB = *(const float2*)(VG + rowB * 64 + c);
            float sum0 = e00 + e10, sum1 = e01 + e11;
            float agg0 = e00 * vgA.x + e10 * vgB.x;
            float agg1 = e01 * vgA.y + e11 * vgB.y;
#pragma unroll
            for (int msk = 4; msk <= 16; msk <<= 1) {
                sum0 += __shfl_xor_sync(0xffffffffu, sum0, msk);
                sum1 += __shfl_xor_sync(0xffffffffu, sum1, msk);
                agg0 += __shfl_xor_sync(0xffffffffu, agg0, msk);
                agg1 += __shfl_xor_sync(0xffffffffu, agg1, msk);
            }
            if (lane < 4) {
                float2 o = make_float2(agg0 / sum0, agg1 / sum1);
                *(float2*)(out + (ib + q) * 64 + c) = o;
            }
        }
    }
}

// ---------------------------------------------------------------------------
extern "C" void kernel_launch(void* const* d_in, const int* in_sizes, int n_in,
                              void* d_out, int out_size) {
    const float* x   = (const float*)d_in[0];
    const float* pos = (const float*)d_in[1];
    const float* Wq  = (const float*)d_in[2];
    const float* Wk  = (const float*)d_in[3];
    const float* Wv  = (const float*)d_in[4];
    const float* P1  = (const float*)d_in[5];
    const float* pb1 = (const float*)d_in[6];
    const float* P2  = (const float*)d_in[7];
    const float* pb2 = (const float*)d_in[8];
    const float* A1  = (const float*)d_in[9];
    const float* ab1 = (const float*)d_in[10];
    const float* A2  = (const float*)d_in[11];
    const float* ab2 = (const float*)d_in[12];
    float* out = (float*)d_out;

    cudaFuncSetAttribute(fused_kernel, cudaFuncAttributeMaxDynamicSharedMemorySize,
                         SMEM_BYTES);
    fused_kernel<<<GRID, NT, SMEM_BYTES>>>(
        x, pos, Wq, Wk, Wv, P1, pb1, P2, pb2, A1, ab1, A2, ab2, out);
}

// round 12
// speedup vs baseline: 1.5371x; 1.0727x over previous
#include <cuda_runtime.h>
#include <cuda_bf16.h>
#include <math.h>
#include <stdint.h>

#define NPTS 1024
#define DIM  64
#define HID  256
#define K    16
#define QB   8
#define RB   128
#define GRID 128
#define NT   512
#define SK   72          // bf16 row stride for all MMA tiles (conflict-free ldmatrix)
#define SPLIT_PER_BLK 288   // (16384 + 16384 + 4096) / 128

__device__ float g_k[NPTS * DIM];
__device__ float g_v[NPTS * DIM];
__device__ unsigned g_bar;   // advances by GRID per launch
// pre-split bf16 weights (written cooperatively each launch, same values)
__device__ unsigned short g_A1hi[HID * DIM], g_A1lo[HID * DIM];   // [n*64+kd]
__device__ unsigned short g_A2hi[HID * DIM], g_A2lo[HID * DIM];   // [ch*4096+n*64+kk]
__device__ unsigned short g_P2hi[DIM * DIM], g_P2lo[DIM * DIM];   // [n*64+kk]

// ---- dynamic smem byte offsets ----
#define VG_OFF  0u          // 32768: fp32 VG[128][64]
#define TA_HI   32768u      // 18432: bf16 T hi [128][SK]
#define TA_LO   51200u      // 18432
#define A1_HI   69632u      // 36864: bf16 A1^T hi [256n][SK]
#define A1_LO   106496u     // 36864
#define A2C_HI  143360u     // 9216:  bf16 A2c^T / P2^T hi [64n][SK]
#define A2C_LO  152576u     // 9216
#define HC_HI   161792u     // 18432: bf16 H-chunk / E hi [128][SK]
#define HC_LO   180224u     // 18432
#define SMEM_BYTES 198656u
// prolog aliases
#define PS_OFF  HC_HI       // pos staging (12288)

// ---------------- helpers ----------------
__device__ __forceinline__ uint32_t smem_u32(const void* p) {
    uint32_t a;
    asm("{ .reg .u64 t; cvta.to.shared.u64 t, %1; cvt.u32.u64 %0, t; }" : "=r"(a) : "l"(p));
    return a;
}
__device__ __forceinline__ void bf16split(float v, unsigned short& hb, unsigned short& lb) {
    __nv_bfloat16 h = __float2bfloat16(v);
    hb = __bfloat16_as_ushort(h);
    __nv_bfloat16 l = __float2bfloat16(v - __bfloat162float(h));
    lb = __bfloat16_as_ushort(l);
}
__device__ __forceinline__ void ldsm4(uint32_t& r0, uint32_t& r1, uint32_t& r2, uint32_t& r3,
                                      uint32_t addr) {
    asm volatile("ldmatrix.sync.aligned.m8n8.x4.shared.b16 {%0,%1,%2,%3}, [%4];"
                 : "=r"(r0), "=r"(r1), "=r"(r2), "=r"(r3) : "r"(addr));
}
__device__ __forceinline__ void mma_bf16(float* c, const uint32_t* a, const uint32_t* b) {
    asm volatile("mma.sync.aligned.m16n8k16.row.col.f32.bf16.bf16.f32 "
                 "{%0,%1,%2,%3},{%4,%5,%6,%7},{%8,%9},{%0,%1,%2,%3};"
                 : "+f"(c[0]), "+f"(c[1]), "+f"(c[2]), "+f"(c[3])
                 : "r"(a[0]), "r"(a[1]), "r"(a[2]), "r"(a[3]), "r"(b[0]), "r"(b[1]));
}
__device__ __forceinline__ uint32_t a_addr(uint32_t base, int r0, int k0, int lane) {
    int row = r0 + (lane & 7) + ((lane >> 3) & 1) * 8;
    int col = k0 + (lane >> 4) * 8;
    return base + (uint32_t)(row * SK + col) * 2u;
}
__device__ __forceinline__ uint32_t b_addr(uint32_t base, int n0, int nfb, int k0, int lane) {
    int g = lane >> 3;
    int row = n0 + (nfb + (g >> 1)) * 8 + (lane & 7);
    int col = k0 + (g & 1) * 8;
    return base + (uint32_t)(row * SK + col) * 2u;
}

// ---------------------------------------------------------------------------
__global__ __launch_bounds__(NT)
void fused_kernel(const float* __restrict__ x,
                  const float* __restrict__ pos,
                  const float* __restrict__ Wq,
                  const float* __restrict__ Wk,
                  const float* __restrict__ Wv,
                  const float* __restrict__ P1, const float* __restrict__ pb1,
                  const float* __restrict__ P2, const float* __restrict__ pb2,
                  const float* __restrict__ A1, const float* __restrict__ ab1,
                  const float* __restrict__ A2, const float* __restrict__ ab2,
                  float* __restrict__ out) {
    extern __shared__ char smc[];
    float* VG  = (float*)(smc + VG_OFF);
    float* ps  = (float*)(smc + PS_OFF);

    __shared__ int   nb[RB];
    __shared__ float rp[RB][3];
    __shared__ float qrow[QB * DIM];
    __shared__ float xs[QB * DIM];
    __shared__ float cval[QB][2][K];
    __shared__ int   cidx[QB][2][K];
    __shared__ unsigned s_ticket;

    int tid = threadIdx.x;
    int ib = blockIdx.x * QB;
    int w = tid >> 5, lane = tid & 31;
    uint32_t sb = smem_u32(smc);

    // ---- Prolog staging: pos, x rows ----
    for (int t = tid; t < NPTS * 3; t += NT) ps[t] = pos[t];
    for (int t = tid; t < QB * DIM; t += NT) xs[t] = x[ib * DIM + t];

    // ---- Weight split producer: this block's 1/128 slice of A1/A2/P2 ----
    if (tid < SPLIT_PER_BLK) {
        int g = blockIdx.x * SPLIT_PER_BLK + tid;
        float v; int idx;
        unsigned short hh, ll;
        if (g < 16384) {
            int n = g & 255, kd = g >> 8;
            v = A1[kd * HID + n];
            idx = n * 64 + kd;
            bf16split(v, hh, ll);
            g_A1hi[idx] = hh; g_A1lo[idx] = ll;
        } else if (g < 32768) {
            int u = g - 16384;
            int n = u & 63, kk = (u >> 6) & 63, ch = u >> 12;
            v = A2[(ch * 64 + kk) * DIM + n];
            idx = ch * 4096 + n * 64 + kk;
            bf16split(v, hh, ll);
            g_A2hi[idx] = hh; g_A2lo[idx] = ll;
        } else {
            int u = g - 32768;
            int n = u & 63, kk = u >> 6;
            v = P2[kk * DIM + n];
            idx = n * 64 + kk;
            bf16split(v, hh, ll);
            g_P2hi[idx] = hh; g_P2lo[idx] = ll;
        }
    }
    __syncthreads();

    // ---- qkv for this block's 8 rows ----
    {
        int r = tid >> 6, d = tid & 63;
        float q = 0.f, kk = 0.f, vv = 0.f;
#pragma unroll 4
        for (int c = 0; c < DIM; c++) {
            float xv = xs[r * DIM + c];
            q  += xv * Wq[c * DIM + d];
            kk += xv * Wk[c * DIM + d];
            vv += xv * Wv[c * DIM + d];
        }
        qrow[r * DIM + d] = q;
        g_k[(ib + r) * DIM + d] = kk;
        g_v[(ib + r) * DIM + d] = vv;
    }
    __syncthreads();
    if (tid == 0) {
        __threadfence();
        s_ticket = atomicAdd(&g_bar, 1u);
    }

    // ---- kNN: 2 warps per query, 512 candidates each ----
    {
        int qq = w >> 1, hh = w & 1;
        int gi = ib + qq;
        float px = ps[gi * 3 + 0], py = ps[gi * 3 + 1], pz = ps[gi * 3 + 2];
        float v[16]; int id[16];
#pragma unroll
        for (int c = 0; c < 16; c++) {
            int j = hh * 512 + c * 32 + lane;
            float dx = px - ps[j * 3 + 0];
            float dy = py - ps[j * 3 + 1];
            float dz = pz - ps[j * 3 + 2];
            v[c] = dx * dx + dy * dy + dz * dz;
            id[c] = j;
        }
        for (int r = 0; r < K; r++) {
            float bv = v[0]; int bi = id[0];
#pragma unroll
            for (int c = 1; c < 16; c++)
                if (v[c] < bv || (v[c] == bv && id[c] < bi)) { bv = v[c]; bi = id[c]; }
#pragma unroll
            for (int off = 16; off > 0; off >>= 1) {
                float ov = __shfl_down_sync(0xffffffffu, bv, off);
                int   oi = __shfl_down_sync(0xffffffffu, bi, off);
                if (ov < bv || (ov == bv && oi < bi)) { bv = ov; bi = oi; }
            }
            bv = __shfl_sync(0xffffffffu, bv, 0);
            bi = __shfl_sync(0xffffffffu, bi, 0);
            if (lane == 0) { cval[qq][hh][r] = bv; cidx[qq][hh][r] = bi; }
#pragma unroll
            for (int c = 0; c < 16; c++) if (id[c] == bi) v[c] = 3.4e38f;
        }
    }
    __syncthreads();
    if ((w & 1) == 0) {
        int qq = w >> 1;
        float mv = cval[qq][lane >> 4][lane & 15];
        int   mi = cidx[qq][lane >> 4][lane & 15];
        for (int r = 0; r < K; r++) {
            float bv = mv; int bi = mi;
#pragma unroll
            for (int off = 16; off > 0; off >>= 1) {
                float ov = __shfl_down_sync(0xffffffffu, bv, off);
                int   oi = __shfl_down_sync(0xffffffffu, bi, off);
                if (ov < bv || (ov == bv && oi < bi)) { bv = ov; bi = oi; }
            }
            bi = __shfl_sync(0xffffffffu, bi, 0);
            if (lane == 0) nb[qq * K + r] = bi;
            if (mi == bi) mv = 3.4e38f;
        }
    }
    __syncthreads();

    for (int t = tid; t < RB * 3; t += NT) {
        int r = t / 3, c = t - r * 3;
        int gi = ib + (r >> 4);
        rp[r][c] = ps[gi * 3 + c] - ps[nb[r] * 3 + c];
    }
    __syncthreads();

    // ---- Phase 1a: E = relu(rp @ P1 + pb1) as bf16 split tiles (overwrites ps) ----
    for (int t = tid; t < RB * 64; t += NT) {
        int r = t >> 6, h = t & 63;
        float e = rp[r][0] * P1[h] + rp[r][1] * P1[64 + h]
                + rp[r][2] * P1[128 + h] + pb1[h];
        e = fmaxf(e, 0.f);
        unsigned short hh, ll; bf16split(e, hh, ll);
        uint32_t so = (uint32_t)(r * SK + h) * 2u;
        *(unsigned short*)(smc + HC_HI + so) = hh;
        *(unsigned short*)(smc + HC_LO + so) = ll;
    }
    if (tid == 0) {     // global barrier: k/v + split weights visible
        unsigned target = (s_ticket / GRID + 1u) * GRID;
        while ((int)(*(volatile unsigned*)&g_bar - target) < 0) { }
        __threadfence();
    }
    __syncthreads();

    // ---- Vectorized copies: P2^T -> A2C region, A1^T -> A1 region ----
    {
        const uint4* p2h = (const uint4*)g_P2hi;
        const uint4* p2l = (const uint4*)g_P2lo;
        for (int t = tid; t < 512; t += NT) {
            int l = t * 8;
            uint32_t off = (uint32_t)((l >> 6) * SK + (l & 63)) * 2u;
            *(uint4*)(smc + A2C_HI + off) = p2h[t];
            *(uint4*)(smc + A2C_LO + off) = p2l[t];
        }
        const uint4* a1h = (const uint4*)g_A1hi;
        const uint4* a1l = (const uint4*)g_A1lo;
        for (int t = tid; t < 2048; t += NT) {
            int l = t * 8;
            uint32_t off = (uint32_t)((l >> 6) * SK + (l & 63)) * 2u;
            *(uint4*)(smc + A1_HI + off) = a1h[t];
            *(uint4*)(smc + A1_LO + off) = a1l[t];
        }
    }
    __syncthreads();

    int r0 = (w & 7) * 16;           // query row-tile (16 rows = one query)
    int n0w = (w >> 3) * 32;         // 32-col half
    int rowA = r0 + (lane >> 2);
    int rowB = rowA + 8;

    // ---- Phase 1b (MMA): rpe = E @ P2 ; T(bf16 split) ; VG ----
    {
        float C1[16];
#pragma unroll
        for (int i = 0; i < 16; i++) C1[i] = 0.f;
#pragma unroll
        for (int ks = 0; ks < 4; ks++) {
            int k0 = ks * 16;
            uint32_t ah[4], al[4];
            ldsm4(ah[0], ah[1], ah[2], ah[3], a_addr(sb + HC_HI, r0, k0, lane));
            ldsm4(al[0], al[1], al[2], al[3], a_addr(sb + HC_LO, r0, k0, lane));
#pragma unroll
            for (int nfp = 0; nfp < 2; nfp++) {
                uint32_t bh[4], bl[4];
                ldsm4(bh[0], bh[1], bh[2], bh[3], b_addr(sb + A2C_HI, n0w, nfp * 2, k0, lane));
                ldsm4(bl[0], bl[1], bl[2], bl[3], b_addr(sb + A2C_LO, n0w, nfp * 2, k0, lane));
                mma_bf16(C1 + nfp * 8,     ah, bh);
                mma_bf16(C1 + nfp * 8,     ah, bl);
                mma_bf16(C1 + nfp * 8,     al, bh);
                mma_bf16(C1 + nfp * 8 + 4, ah, bh + 2);
                mma_bf16(C1 + nfp * 8 + 4, ah, bl + 2);
                mma_bf16(C1 + nfp * 8 + 4, al, bh + 2);
            }
        }
        // epilogue: T = q - k + rpe (split to TA), VG = v + rpe
        int qq = w & 7;
        int j0 = nb[rowA], j1 = nb[rowB];
#pragma unroll
        for (int nf = 0; nf < 4; nf++) {
            int c = n0w + nf * 8 + 2 * (lane & 3);
            float2 b2 = *(const float2*)(pb2 + c);
            float2 qv = *(const float2*)(qrow + qq * 64 + c);
            float2 k0v = *(const float2*)(g_k + j0 * 64 + c);
            float2 k1v = *(const float2*)(g_k + j1 * 64 + c);
            float2 v0v = *(const float2*)(g_v + j0 * 64 + c);
            float2 v1v = *(const float2*)(g_v + j1 * 64 + c);
            float rpe00 = C1[nf * 4 + 0] + b2.x, rpe01 = C1[nf * 4 + 1] + b2.y;
            float rpe10 = C1[nf * 4 + 2] + b2.x, rpe11 = C1[nf * 4 + 3] + b2.y;
            *(float2*)(VG + rowA * 64 + c) = make_float2(v0v.x + rpe00, v0v.y + rpe01);
            *(float2*)(VG + rowB * 64 + c) = make_float2(v1v.x + rpe10, v1v.y + rpe11);
            float t00 = qv.x - k0v.x + rpe00;
            float t01 = qv.y - k0v.y + rpe01;
            float t10 = qv.x - k1v.x + rpe10;
            float t11 = qv.y - k1v.y + rpe11;
            unsigned short h00, l00, h01, l01, h10, l10, h11, l11;
            bf16split(t00, h00, l00); bf16split(t01, h01, l01);
            bf16split(t10, h10, l10); bf16split(t11, h11, l11);
            uint32_t soA = (uint32_t)(rowA * SK + c) * 2u;
            uint32_t soB = (uint32_t)(rowB * SK + c) * 2u;
            *(uint32_t*)(smc + TA_HI + soA) = (uint32_t)h00 | ((uint32_t)h01 << 16);
            *(uint32_t*)(smc + TA_LO + soA) = (uint32_t)l00 | ((uint32_t)l01 << 16);
            *(uint32_t*)(smc + TA_HI + soB) = (uint32_t)h10 | ((uint32_t)h11 << 16);
            *(uint32_t*)(smc + TA_LO + soB) = (uint32_t)l10 | ((uint32_t)l11 << 16);
        }
    }
    __syncthreads();

    // ---- Chunked MMA: phases 2+3 over 4 chunks of 64 HID cols ----
    float C3[16];
#pragma unroll
    for (int i = 0; i < 16; i++) C3[i] = 0.f;

    for (int chunk = 0; chunk < 4; chunk++) {
        // vectorized copy of A2 chunk (chunk 0 overwrites P2^T — phase 1b done)
        {
            const uint4* c2h = (const uint4*)(g_A2hi + chunk * 4096);
            const uint4* c2l = (const uint4*)(g_A2lo + chunk * 4096);
            for (int t = tid; t < 512; t += NT) {
                int l = t * 8;
                uint32_t off = (uint32_t)((l >> 6) * SK + (l & 63)) * 2u;
                *(uint4*)(smc + A2C_HI + off) = c2h[t];
                *(uint4*)(smc + A2C_LO + off) = c2l[t];
            }
        }

        // ---- Phase 2: C2 = T @ A1[:, chunk cols n0w..n0w+32) ----
        float C2[16];
#pragma unroll
        for (int i = 0; i < 16; i++) C2[i] = 0.f;
        int bn0 = chunk * 64 + n0w;
#pragma unroll
        for (int ks = 0; ks < 4; ks++) {
            int k0 = ks * 16;
            uint32_t ah[4], al[4];
            ldsm4(ah[0], ah[1], ah[2], ah[3], a_addr(sb + TA_HI, r0, k0, lane));
            ldsm4(al[0], al[1], al[2], al[3], a_addr(sb + TA_LO, r0, k0, lane));
#pragma unroll
            for (int nfp = 0; nfp < 2; nfp++) {
                uint32_t bh[4], bl[4];
                ldsm4(bh[0], bh[1], bh[2], bh[3], b_addr(sb + A1_HI, bn0, nfp * 2, k0, lane));
                ldsm4(bl[0], bl[1], bl[2], bl[3], b_addr(sb + A1_LO, bn0, nfp * 2, k0, lane));
                mma_bf16(C2 + nfp * 8,     ah, bh);
                mma_bf16(C2 + nfp * 8,     ah, bl);
                mma_bf16(C2 + nfp * 8,     al, bh);
                mma_bf16(C2 + nfp * 8 + 4, ah, bh + 2);
                mma_bf16(C2 + nfp * 8 + 4, ah, bl + 2);
                mma_bf16(C2 + nfp * 8 + 4, al, bh + 2);
            }
        }
        __syncthreads();   // prior-chunk H reads done; A2c staged

        // bias + relu + bf16 split -> H chunk
        {
            int cbase = n0w + 2 * (lane & 3);
#pragma unroll
            for (int nf = 0; nf < 4; nf++) {
                int cl = cbase + nf * 8;
                float2 bias = *(const float2*)(ab1 + chunk * 64 + cl);
                float v00 = fmaxf(C2[nf * 4 + 0] + bias.x, 0.f);
                float v01 = fmaxf(C2[nf * 4 + 1] + bias.y, 0.f);
                float v10 = fmaxf(C2[nf * 4 + 2] + bias.x, 0.f);
                float v11 = fmaxf(C2[nf * 4 + 3] + bias.y, 0.f);
                unsigned short h00, l00, h01, l01, h10, l10, h11, l11;
                bf16split(v00, h00, l00); bf16split(v01, h01, l01);
                bf16split(v10, h10, l10); bf16split(v11, h11, l11);
                uint32_t soA = (uint32_t)(rowA * SK + cl) * 2u;
                uint32_t soB = (uint32_t)(rowB * SK + cl) * 2u;
                *(uint32_t*)(smc + HC_HI + soA) = (uint32_t)h00 | ((uint32_t)h01 << 16);
                *(uint32_t*)(smc + HC_LO + soA) = (uint32_t)l00 | ((uint32_t)l01 << 16);
                *(uint32_t*)(smc + HC_HI + soB) = (uint32_t)h10 | ((uint32_t)h11 << 16);
                *(uint32_t*)(smc + HC_LO + soB) = (uint32_t)l10 | ((uint32_t)l11 << 16);
            }
        }
        __syncthreads();

        // ---- Phase 3: C3 += H_chunk @ A2_chunk ----
#pragma unroll
        for (int ks = 0; ks < 4; ks++) {
            int k0 = ks * 16;
            uint32_t ah[4], al[4];
            ldsm4(ah[0], ah[1], ah[2], ah[3], a_addr(sb + HC_HI, r0, k0, lane));
            ldsm4(al[0], al[1], al[2], al[3], a_addr(sb + HC_LO, r0, k0, lane));
#pragma unroll
            for (int nfp = 0; nfp < 2; nfp++) {
                uint32_t bh[4], bl[4];
                ldsm4(bh[0], bh[1], bh[2], bh[3], b_addr(sb + A2C_HI, n0w, nfp * 2, k0, lane));
                ldsm4(bl[0], bl[1], bl[2], bl[3], b_addr(sb + A2C_LO, n0w, nfp * 2, k0, lane));
                mma_bf16(C3 + nfp * 8,     ah, bh);
                mma_bf16(C3 + nfp * 8,     ah, bl);
                mma_bf16(C3 + nfp * 8,     al, bh);
                mma_bf16(C3 + nfp * 8 + 4, ah, bh + 2);
                mma_bf16(C3 + nfp * 8 + 4, ah, bl + 2);
                mma_bf16(C3 + nfp * 8 + 4, al, bh + 2);
            }
        }
        __syncthreads();   // before restaging A2c / rewriting H
    }

    // ---- Phase 4: softmax over 16 neighbors (register fragments + shfl) ----
    {
        int q = w & 7;
#pragma unroll
        for (int nf = 0; nf < 4; nf++) {
            int c = n0w + nf * 8 + 2 * (lane & 3);
            float2 b2 = *(const float2*)(ab2 + c);
            float s00 = C3[nf * 4 + 0] + b2.x;
            float s01 = C3[nf * 4 + 1] + b2.y;
            float s10 = C3[nf * 4 + 2] + b2.x;
            float s11 = C3[nf * 4 + 3] + b2.y;
            float m0 = fmaxf(s00, s10);
            float m1 = fmaxf(s01, s11);
#pragma unroll
            for (int msk = 4; msk <= 16; msk <<= 1) {
                m0 = fmaxf(m0, __shfl_xor_sync(0xffffffffu, m0, msk));
                m1 = fmaxf(m1, __shfl_xor_sync(0xffffffffu, m1, msk));
            }
            float e00 = __expf(s00 - m0), e10 = __expf(s10 - m0);
            float e01 = __expf(s01 - m1), e11 = __expf(s11 - m1);
            float2 vgA = *(const float2*)(VG + rowA * 64 + c);
            float2 vgB = *(const float2*)(VG + rowB * 64 + c);
            float sum0 = e00 + e10, sum1 = e01 + e11;
            float agg0 = e00 * vgA.x + e10 * vgB.x;
            float agg1 = e01 * vgA.y + e11 * vgB.y;
#pragma unroll
            for (int msk = 4; msk <= 16; msk <<= 1) {
                sum0 += __shfl_xor_sync(0xffffffffu, sum0, msk);
                sum1 += __shfl_xor_sync(0xffffffffu, sum1, msk);
                agg0 += __shfl_xor_sync(0xffffffffu, agg0, msk);
                agg1 += __shfl_xor_sync(0xffffffffu, agg1, msk);
            }
            if (lane < 4) {
                float2 o = make_float2(agg0 / sum0, agg1 / sum1);
                *(float2*)(out + (ib + q) * 64 + c) = o;
            }
        }
    }
}

// ---------------------------------------------------------------------------
extern "C" void kernel_launch(void* const* d_in, const int* in_sizes, int n_in,
                              void* d_out, int out_size) {
    const float* x   = (const float*)d_in[0];
    const float* pos = (const float*)d_in[1];
    const float* Wq  = (const float*)d_in[2];
    const float* Wk  = (const float*)d_in[3];
    const float* Wv  = (const float*)d_in[4];
    const float* P1  = (const float*)d_in[5];
    const float* pb1 = (const float*)d_in[6];
    const float* P2  = (const float*)d_in[7];
    const float* pb2 = (const float*)d_in[8];
    const float* A1  = (const float*)d_in[9];
    const float* ab1 = (const float*)d_in[10];
    const float* A2  = (const float*)d_in[11];
    const float* ab2 = (const float*)d_in[12];
    float* out = (float*)d_out;

    cudaFuncSetAttribute(fused_kernel, cudaFuncAttributeMaxDynamicSharedMemorySize,
                         SMEM_BYTES);
    fused_kernel<<<GRID, NT, SMEM_BYTES>>>(
        x, pos, Wq, Wk, Wv, P1, pb1, P2, pb2, A1, ab1, A2, ab2, out);
}